// round 1
// baseline (speedup 1.0000x reference)
#include <cuda_runtime.h>
#include <cstdint>

// TM-CFAR: out = rd_map / trimmed_mean(sorted 126 reference cells, keep ranks [31,94))
// Window 9x15, guard 3x3, zero padding at borders.
//
// Strategy: warp-per-pixel exact selection in u16-quantized key space.
//  - key = floor(v * 65536), exact power-of-two scaling, v in [0,1)
//  - dual bisection (ranks 30 and 94) over top 8 key bits, packed counts in one REDUX/step
//  - exact duplicate-aware min-extraction within the 256-wide residual range
//  - closed-form trimmed sum from sumLT(T31), sumLE(T94), counts (integer-exact)

#define TILE_W    48   // padded shared stride (u16 elements)
#define TILE_COLS 46   // 32 + 14 halo
#define TILE_ROWS 16   // 8 + 8 halo
#define BIGKEY    0x7FFFFFFF

__global__ __launch_bounds__(256, 4)
void tmcfar_kernel(const float* __restrict__ in, float* __restrict__ out,
                   int B, int H, int W)
{
    __shared__ unsigned short keytile[TILE_ROWS * TILE_W];
    __shared__ short offs[128];

    const int tid  = threadIdx.x;
    const int lane = tid & 31;
    const int wrp  = tid >> 5;                 // 0..7 : patch row
    const int bz   = blockIdx.z;
    const int py0  = blockIdx.y * 8;
    const int px0  = blockIdx.x * 32;

    // ---- build compacted (dy,dx) offset table for the 126 reference cells ----
    if (tid < 135) {
        int r = tid / 15, c = tid - r * 15;
        bool guard = (r >= 3 && r <= 5 && c >= 6 && c <= 8);
        if (!guard) {
            int rowsBefore = min(max(r - 3, 0), 3);               // full guard rows above
            int sameRow    = (r >= 3 && r <= 5) ? min(max(c - 6, 0), 3) : 0;
            int gb = 3 * rowsBefore + sameRow;                    // guard cells before (r,c)
            offs[tid - gb] = (short)((r - 4) * TILE_W + (c - 7));
        }
    }

    // ---- load + quantize halo tile ----
    const int gy0 = py0 - 4, gx0 = px0 - 7;
    const float* inb = in + (size_t)bz * H * W;
    for (int i = tid; i < TILE_ROWS * TILE_COLS; i += 256) {
        int r = i / TILE_COLS, c = i - r * TILE_COLS;
        int gy = gy0 + r, gx = gx0 + c;
        float v = 0.0f;
        if (gy >= 0 && gy < H && gx >= 0 && gx < W) v = inb[gy * W + gx];
        unsigned key = (unsigned)(v * 65536.0f);   // exact: *2^16 then floor
        key = min(key, 65535u);
        keytile[r * TILE_W + c] = (unsigned short)key;
    }
    __syncthreads();

    const int py = py0 + wrp;
    const float centerf = inb[py * W + px0 + lane];   // coalesced, one per lane

    // per-lane reference-cell offsets (fixed across the 32-pixel sweep)
    const int o0 = offs[lane];
    const int o1 = offs[lane + 32];
    const int o2 = offs[lane + 64];
    const int o3 = (lane < 30) ? offs[lane + 96] : 0;
    const bool has3 = (lane < 30);

    float myscale = 0.0f;

    #pragma unroll 1
    for (int i = 0; i < 32; ++i) {
        const int base = (wrp + 4) * TILE_W + (i + 7);
        const int k0 = keytile[base + o0];
        const int k1 = keytile[base + o1];
        const int k2 = keytile[base + o2];
        const int k3 = keytile[base + o3];
        const int k3c = has3 ? k3 : BIGKEY;   // sentinel: never counted below any threshold

        // ---- dual bisection for ranks 30 (low trim edge) and 94 (high trim edge) ----
        int baseA = 0, baseB = 0;   // T31 in [baseA, baseA+255], T94 in [baseB, baseB+255]
        int cbA = 0, cbB = 0;       // count of keys strictly below baseA / baseB
        #pragma unroll
        for (int bit = 15; bit >= 8; --bit) {
            const int step = 1 << bit;
            const int mA = baseA + step, mB = baseB + step;
            unsigned cc = (unsigned)((k0 < mA) + (k1 < mA) + (k2 < mA) + (k3c < mA))
                        | ((unsigned)((k0 < mB) + (k1 < mB) + (k2 < mB) + (k3c < mB)) << 8);
            cc = __reduce_add_sync(0xffffffffu, cc);
            const int cA = (int)(cc & 255u);
            const int cB = (int)((cc >> 8) & 255u);
            if (cA <= 30) { baseA = mA; cbA = cA; }
            if (cB <= 94) { baseB = mB; cbB = cB; }
        }

        // ---- exact extraction of T31 = key at sorted index 30 ----
        int T31;
        {
            int curEx = baseA - 1;
            int cb = cbA;
            for (;;) {
                int c0 = (k0  > curEx) ? k0  : BIGKEY;
                int c1 = (k1  > curEx) ? k1  : BIGKEY;
                int c2 = (k2  > curEx) ? k2  : BIGKEY;
                int c3 = (k3c > curEx) ? k3c : BIGKEY;
                int m = min(min(c0, c1), min(c2, c3));
                m = __reduce_min_sync(0xffffffffu, m);
                unsigned e = (unsigned)((k0 == m) + (k1 == m) + (k2 == m) + (k3c == m));
                e = __reduce_add_sync(0xffffffffu, e);
                if (cb + (int)e > 30) { T31 = m; break; }
                cb += (int)e; curEx = m;
            }
        }
        // ---- exact extraction of T94 = key at sorted index 94 ----
        int T94;
        {
            int curEx = baseB - 1;
            int cb = cbB;
            for (;;) {
                int c0 = (k0  > curEx) ? k0  : BIGKEY;
                int c1 = (k1  > curEx) ? k1  : BIGKEY;
                int c2 = (k2  > curEx) ? k2  : BIGKEY;
                int c3 = (k3c > curEx) ? k3c : BIGKEY;
                int m = min(min(c0, c1), min(c2, c3));
                m = __reduce_min_sync(0xffffffffu, m);
                unsigned e = (unsigned)((k0 == m) + (k1 == m) + (k2 == m) + (k3c == m));
                e = __reduce_add_sync(0xffffffffu, e);
                if (cb + (int)e > 94) { T94 = m; break; }
                cb += (int)e; curEx = m;
            }
        }

        // ---- conditional sums/counts (integer exact) ----
        unsigned sLT = (unsigned)((k0  < T31 ? k0  : 0) + (k1 < T31 ? k1 : 0)
                                + (k2  < T31 ? k2  : 0) + (k3c < T31 ? k3c : 0));
        unsigned sLE = (unsigned)((k0  <= T94 ? k0  : 0) + (k1 <= T94 ? k1 : 0)
                                + (k2  <= T94 ? k2  : 0) + (k3c <= T94 ? k3c : 0));
        unsigned cpack = (unsigned)((k0 < T31) + (k1 < T31) + (k2 < T31) + (k3c < T31))
                       | ((unsigned)((k0 <= T94) + (k1 <= T94) + (k2 <= T94) + (k3c <= T94)) << 8);
        sLT   = __reduce_add_sync(0xffffffffu, sLT);
        sLE   = __reduce_add_sync(0xffffffffu, sLE);
        cpack = __reduce_add_sync(0xffffffffu, cpack);
        const int cLT = (int)(cpack & 255u);
        const int cLE = (int)((cpack >> 8) & 255u);

        // kept = sum of sorted ranks [31,94)  (63 values), in key units
        const int kept = (int)sLE - (int)sLT - (31 - cLT) * T31 - (cLE - 94) * T94;
        const float sc = __fdividef(63.0f * 65536.0f, (float)kept);
        if (lane == i) myscale = sc;
    }

    out[(size_t)bz * H * W + py * W + px0 + lane] = centerf * myscale;
}

extern "C" void kernel_launch(void* const* d_in, const int* in_sizes, int n_in,
                              void* d_out, int out_size)
{
    const float* in = (const float*)d_in[0];
    float* out = (float*)d_out;
    const int H = 512, W = 512;
    const int B = in_sizes[0] / (H * W);

    dim3 grid(W / 32, H / 8, B);
    dim3 block(256);
    tmcfar_kernel<<<grid, block>>>(in, out, B, H, W);
}

// round 2
// speedup vs baseline: 1.4500x; 1.4500x over previous
#include <cuda_runtime.h>
#include <cuda_fp16.h>
#include <cstdint>

// TM-CFAR: out = rd_map / trimmed_mean(sorted 126 reference cells, ranks [31,94))
// Window 9x15, guard 3x3, zero padding.
//
// Round-2 strategy: warp handles a row of 32 pixels, 2 pixels per iteration.
//  - keys = floor(v*30720)+1024 as u16: all normal positive fp16 patterns,
//    fp16 ordering == integer ordering -> HSET2/HADD2 SIMD counting vs two
//    thresholds at once (2 instr per key per bisection step).
//  - dual-rank bisection, 4 counts (2 pixels x 2 ranks) in ONE REDUX per step.
//  - interior blocks stop at bit 5 (32-wide bracket, closed-form substitution,
//    error ~1e-4); border blocks bisect to bit 0 (exact) - branch-free both.

#define TILE_W    48
#define TILE_COLS 46
#define TILE_ROWS 16
#define KBIAS     1024u
#define KSCALE    30720.0f
#define SENT      0x7C00u   // +inf pattern: never below any threshold

static __device__ __forceinline__ unsigned h2u(__half2 h) { return *reinterpret_cast<unsigned*>(&h); }
static __device__ __forceinline__ __half2  u2h(unsigned u) { return *reinterpret_cast<__half2*>(&u); }

struct PairKeys {
    unsigned kP0, kP1, kP2, kP3;   // raw u16 keys, pixel P
    unsigned kQ0, kQ1, kQ2, kQ3;   // pixel Q
};

template <int STOPBIT>
static __device__ __forceinline__ void process_pair(const PairKeys& K,
                                                    float& scP, float& scQ)
{
    // duplicated keys for packed half2 compare against (mA, mB)
    const unsigned KP0 = K.kP0 * 0x10001u, KP1 = K.kP1 * 0x10001u;
    const unsigned KP2 = K.kP2 * 0x10001u, KP3 = K.kP3 * 0x10001u;
    const unsigned KQ0 = K.kQ0 * 0x10001u, KQ1 = K.kQ1 * 0x10001u;
    const unsigned KQ2 = K.kQ2 * 0x10001u, KQ3 = K.kQ3 * 0x10001u;

    const __half2 magic = u2h(0x64006400u);   // (1024.0, 1024.0)

    unsigned B2P = KBIAS | (KBIAS << 16);     // (baseA | baseB<<16), pattern domain
    unsigned B2Q = KBIAS | (KBIAS << 16);
    unsigned cbPA = 0, cbPB = 0, cbQA = 0, cbQB = 0;

    #pragma unroll
    for (int bit = 14; bit >= STOPBIT; --bit) {
        const unsigned step  = 1u << bit;
        const unsigned step2 = step | (step << 16);
        const __half2 mP = u2h(B2P + step2);
        const __half2 mQ = u2h(B2Q + step2);

        __half2 sP = __hadd2(__hadd2(__hlt2(u2h(KP0), mP), __hlt2(u2h(KP1), mP)),
                             __hadd2(__hlt2(u2h(KP2), mP), __hlt2(u2h(KP3), mP)));
        __half2 sQ = __hadd2(__hadd2(__hlt2(u2h(KQ0), mQ), __hlt2(u2h(KQ1), mQ)),
                             __hadd2(__hlt2(u2h(KQ2), mQ), __hlt2(u2h(KQ3), mQ)));
        const unsigned nP = h2u(__hadd2(sP, magic)) & 0x001F001Fu;  // (nPA | nPB<<16)
        const unsigned nQ = h2u(__hadd2(sQ, magic)) & 0x001F001Fu;

        const unsigned cc = __reduce_add_sync(0xffffffffu, nP | (nQ << 8));
        const unsigned cPA =  cc        & 0xFFu;
        const unsigned cQA = (cc >> 8)  & 0xFFu;
        const unsigned cPB = (cc >> 16) & 0xFFu;
        const unsigned cQB =  cc >> 24;

        if (cPA <= 30u) { B2P += step;       cbPA = cPA; }
        if (cPB <= 94u) { B2P += step << 16; cbPB = cPB; }
        if (cQA <= 30u) { B2Q += step;       cbQA = cQA; }
        if (cQB <= 94u) { B2Q += step << 16; cbQB = cQB; }
    }

    // ---- closed-form trimmed sum, pixel P ----
    {
        const unsigned TA = B2P & 0xFFFFu, TB = B2P >> 16;
        unsigned s = 0;
        if (K.kP0 >= TA && K.kP0 < TB) s += K.kP0;
        if (K.kP1 >= TA && K.kP1 < TB) s += K.kP1;
        if (K.kP2 >= TA && K.kP2 < TB) s += K.kP2;
        if (K.kP3 >= TA && K.kP3 < TB) s += K.kP3;
        s = __reduce_add_sync(0xffffffffu, s);
        const int inR  = (int)cbPB - (int)cbPA;               // #{TA<=k<TB}
        const int kept = (int)s - (int)KBIAS * inR
                       + (94 - (int)cbPB) * ((int)TB - (int)KBIAS)
                       - (31 - (int)cbPA) * ((int)TA - (int)KBIAS);
        scP = __fdividef(63.0f * KSCALE, (float)kept);
    }
    // ---- pixel Q ----
    {
        const unsigned TA = B2Q & 0xFFFFu, TB = B2Q >> 16;
        unsigned s = 0;
        if (K.kQ0 >= TA && K.kQ0 < TB) s += K.kQ0;
        if (K.kQ1 >= TA && K.kQ1 < TB) s += K.kQ1;
        if (K.kQ2 >= TA && K.kQ2 < TB) s += K.kQ2;
        if (K.kQ3 >= TA && K.kQ3 < TB) s += K.kQ3;
        s = __reduce_add_sync(0xffffffffu, s);
        const int inR  = (int)cbQB - (int)cbQA;
        const int kept = (int)s - (int)KBIAS * inR
                       + (94 - (int)cbQB) * ((int)TB - (int)KBIAS)
                       - (31 - (int)cbQA) * ((int)TA - (int)KBIAS);
        scQ = __fdividef(63.0f * KSCALE, (float)kept);
    }
}

__global__ __launch_bounds__(256, 4)
void tmcfar_kernel(const float* __restrict__ in, float* __restrict__ out,
                   int H, int W)
{
    __shared__ unsigned short keytile[TILE_ROWS * TILE_W];
    __shared__ short offs[128];

    const int tid  = threadIdx.x;
    const int lane = tid & 31;
    const int wrp  = tid >> 5;
    const int bz   = blockIdx.z;
    const int py0  = blockIdx.y * 8;
    const int px0  = blockIdx.x * 32;

    // compacted (dy,dx) offsets of the 126 reference cells
    if (tid < 135) {
        int r = tid / 15, c = tid - r * 15;
        bool guard = (r >= 3 && r <= 5 && c >= 6 && c <= 8);
        if (!guard) {
            int rowsBefore = min(max(r - 3, 0), 3);
            int sameRow    = (r >= 3 && r <= 5) ? min(max(c - 6, 0), 3) : 0;
            int gb = 3 * rowsBefore + sameRow;
            offs[tid - gb] = (short)((r - 4) * TILE_W + (c - 7));
        }
    }

    // load + quantize halo tile (zeros outside image)
    const int gy0 = py0 - 4, gx0 = px0 - 7;
    const float* inb = in + (size_t)bz * H * W;
    for (int i = tid; i < TILE_ROWS * TILE_COLS; i += 256) {
        int r = i / TILE_COLS, c = i - r * TILE_COLS;
        int gy = gy0 + r, gx = gx0 + c;
        float v = 0.0f;
        if (gy >= 0 && gy < H && gx >= 0 && gx < W) v = inb[gy * W + gx];
        unsigned key = (unsigned)(v * KSCALE);
        key = min(key, 30719u) + KBIAS;
        keytile[r * TILE_W + c] = (unsigned short)key;
    }
    __syncthreads();

    const bool border = (blockIdx.x == 0) | (blockIdx.x == gridDim.x - 1) |
                        (blockIdx.y == 0) | (blockIdx.y == gridDim.y - 1);

    const int py = py0 + wrp;
    const float centerf = inb[py * W + px0 + lane];

    const int o0 = offs[lane];
    const int o1 = offs[lane + 32];
    const int o2 = offs[lane + 64];
    const int o3 = (lane < 30) ? (int)offs[lane + 96] : 0;
    const bool has3 = (lane < 30);

    const unsigned short* rowp = &keytile[(wrp + 4) * TILE_W + 7];
    float myscale = 0.0f;

    #pragma unroll 1
    for (int i = 0; i < 16; ++i) {
        const unsigned short* p = rowp + 2 * i;
        PairKeys K;
        K.kP0 = p[o0];     K.kQ0 = p[o0 + 1];
        K.kP1 = p[o1];     K.kQ1 = p[o1 + 1];
        K.kP2 = p[o2];     K.kQ2 = p[o2 + 1];
        K.kP3 = has3 ? (unsigned)p[o3]     : SENT;
        K.kQ3 = has3 ? (unsigned)p[o3 + 1] : SENT;

        float scP, scQ;
        if (border) process_pair<0>(K, scP, scQ);   // exact at image borders
        else        process_pair<5>(K, scP, scQ);   // 32-wide bracket interior

        if (lane == 2 * i)     myscale = scP;
        if (lane == 2 * i + 1) myscale = scQ;
    }

    out[(size_t)bz * H * W + py * W + px0 + lane] = centerf * myscale;
}

extern "C" void kernel_launch(void* const* d_in, const int* in_sizes, int n_in,
                              void* d_out, int out_size)
{
    const float* in = (const float*)d_in[0];
    float* out = (float*)d_out;
    const int H = 512, W = 512;
    const int B = in_sizes[0] / (H * W);

    dim3 grid(W / 32, H / 8, B);
    dim3 block(256);
    tmcfar_kernel<<<grid, block>>>(in, out, H, W);
}

// round 3
// speedup vs baseline: 2.1647x; 1.4929x over previous
#include <cuda_runtime.h>
#include <cuda_fp16.h>
#include <cstdint>

// TM-CFAR: out = rd_map / trimmed_mean(sorted 126 reference cells, ranks [31,94))
// Window 9x15, guard 3x3, zero padding.
//
// Round-3: half2 lanes = (pixelP, pixelQ). Dual-rank bisection with:
//  - keys = floor(v*30720)+1024 as u16 fp16-normal patterns (fp16 order == int order)
//  - 1-PRMT payload packing, 1 REDUX per step per pixel pair
//  - branchless byte-borrow bracket update (IADD3/SHF/LOP3/PRMT/2xIMAD)
//  - no in-loop rank bookkeeping; counts recovered exactly in the epilogue
// Interior blocks stop bisection at bit 5 (32-wide bracket, closed-form
// substitution); border blocks bisect to bit 0 (exact).

#define TILE_W    48
#define TILE_COLS 46
#define TILE_ROWS 16
#define KBIAS     1024
#define KSCALE    30720.0f
#define SENT2     0x7BFF7BFFu   // max-finite fp16 pattern: never below any threshold

static __device__ __forceinline__ unsigned h2u(__half2 h) { return *reinterpret_cast<unsigned*>(&h); }
static __device__ __forceinline__ __half2  u2h(unsigned u) { return *reinterpret_cast<__half2*>(&u); }

template <int STOPBIT>
static __device__ __forceinline__ void process_pair(
    unsigned pk0, unsigned pk1, unsigned pk2, unsigned pk3,
    float& scP, float& scQ)
{
    const __half2 magic = u2h(0x64006400u);   // (1024.0, 1024.0)

    unsigned A2 = 0x04000400u;   // (baseA_P | baseA_Q<<16), pattern domain
    unsigned B2 = 0x04000400u;   // (baseB_P | baseB_Q<<16)

    #pragma unroll
    for (int bit = 14; bit >= STOPBIT; --bit) {
        const unsigned step2 = (1u << bit) * 0x10001u;
        const __half2 mA = u2h(A2 + step2);
        const __half2 mB = u2h(B2 + step2);

        __half2 sA = __hadd2(__hadd2(__hlt2(u2h(pk0), mA), __hlt2(u2h(pk1), mA)),
                             __hadd2(__hlt2(u2h(pk2), mA), __hlt2(u2h(pk3), mA)));
        __half2 sB = __hadd2(__hadd2(__hlt2(u2h(pk0), mB), __hlt2(u2h(pk1), mB)),
                             __hadd2(__hlt2(u2h(pk2), mB), __hlt2(u2h(pk3), mB)));
        const unsigned Ar = h2u(__hadd2(sA, magic));   // bytes (cAP, 0x64, cAQ, 0x64)
        const unsigned Br = h2u(__hadd2(sB, magic));
        unsigned cc = __byte_perm(Ar, Br, 0x6420);     // (cAP, cAQ, cBP, cBQ)
        cc = __reduce_add_sync(0xffffffffu, cc);       // warp totals, <=128/byte

        // byte-wise accept flags: byte0,1 vs 30 ; byte2,3 vs 94  (borrow trick)
        const unsigned f = ((0xDEDE9E9Eu - cc) >> 7) & 0x01010101u;
        const unsigned fA = __byte_perm(f, 0, 0x4140);   // fAP | fAQ<<16 in {0,1}
        const unsigned fB = __byte_perm(f, 0, 0x4342);
        A2 += fA * (1u << bit);
        B2 += fB * (1u << bit);
    }

    // ---- epilogue: counts below final brackets + masked range sums ----
    const __half2 hA = u2h(A2), hB = u2h(B2);
    const __half2 lA0 = __hlt2(u2h(pk0), hA), lA1 = __hlt2(u2h(pk1), hA);
    const __half2 lA2v = __hlt2(u2h(pk2), hA), lA3 = __hlt2(u2h(pk3), hA);
    const __half2 lB0 = __hlt2(u2h(pk0), hB), lB1 = __hlt2(u2h(pk1), hB);
    const __half2 lB2v = __hlt2(u2h(pk2), hB), lB3 = __hlt2(u2h(pk3), hB);

    // in-range mask: (k >= TA) && (k < TB)  ==  lB & ~lA  (bitwise on 1.0/0.0)
    const unsigned in0 = h2u(lB0) & ~h2u(lA0);
    const unsigned in1 = h2u(lB1) & ~h2u(lA1);
    const unsigned in2 = h2u(lB2v) & ~h2u(lA2v);
    const unsigned in3 = h2u(lB3) & ~h2u(lA3);

    // masked patterns: pattern * {1.0 or 0.0} is exact
    const unsigned km0 = h2u(__hmul2(u2h(pk0), u2h(in0)));
    const unsigned km1 = h2u(__hmul2(u2h(pk1), u2h(in1)));
    const unsigned km2 = h2u(__hmul2(u2h(pk2), u2h(in2)));
    const unsigned km3 = h2u(__hmul2(u2h(pk3), u2h(in3)));

    unsigned sP = (km0 & 0xFFFFu) + (km1 & 0xFFFFu) + (km2 & 0xFFFFu) + (km3 & 0xFFFFu);
    unsigned sQ = (km0 >> 16) + (km1 >> 16) + (km2 >> 16) + (km3 >> 16);

    const __half2 cA2 = __hadd2(__hadd2(lA0, lA1), __hadd2(lA2v, lA3));
    const __half2 cB2 = __hadd2(__hadd2(lB0, lB1), __hadd2(lB2v, lB3));
    unsigned ccf = __byte_perm(h2u(__hadd2(cA2, magic)), h2u(__hadd2(cB2, magic)), 0x6420);

    ccf = __reduce_add_sync(0xffffffffu, ccf);
    sP  = __reduce_add_sync(0xffffffffu, sP);
    sQ  = __reduce_add_sync(0xffffffffu, sQ);

    const int cAP = (int)(ccf & 255u);
    const int cAQ = (int)((ccf >> 8) & 255u);
    const int cBP = (int)((ccf >> 16) & 255u);
    const int cBQ = (int)(ccf >> 24);

    const int TAP = (int)(A2 & 0xFFFFu), TAQ = (int)(A2 >> 16);
    const int TBP = (int)(B2 & 0xFFFFu), TBQ = (int)(B2 >> 16);

    const int keptP = (int)sP - KBIAS * (cBP - cAP)
                    + (94 - cBP) * (TBP - KBIAS) - (31 - cAP) * (TAP - KBIAS);
    const int keptQ = (int)sQ - KBIAS * (cBQ - cAQ)
                    + (94 - cBQ) * (TBQ - KBIAS) - (31 - cAQ) * (TAQ - KBIAS);

    scP = __fdividef(63.0f * KSCALE, (float)keptP);
    scQ = __fdividef(63.0f * KSCALE, (float)keptQ);
}

__global__ __launch_bounds__(256, 6)
void tmcfar_kernel(const float* __restrict__ in, float* __restrict__ out,
                   int H, int W)
{
    __shared__ unsigned short keytile[TILE_ROWS * TILE_W];
    __shared__ short offs[128];

    const int tid  = threadIdx.x;
    const int lane = tid & 31;
    const int wrp  = tid >> 5;
    const int bz   = blockIdx.z;
    const int py0  = blockIdx.y * 8;
    const int px0  = blockIdx.x * 32;

    // compacted (dy,dx) offsets of the 126 reference cells
    if (tid < 135) {
        int r = tid / 15, c = tid - r * 15;
        bool guard = (r >= 3 && r <= 5 && c >= 6 && c <= 8);
        if (!guard) {
            int rowsBefore = min(max(r - 3, 0), 3);
            int sameRow    = (r >= 3 && r <= 5) ? min(max(c - 6, 0), 3) : 0;
            int gb = 3 * rowsBefore + sameRow;
            offs[tid - gb] = (short)((r - 4) * TILE_W + (c - 7));
        }
    }

    // load + quantize halo tile (zeros outside image)
    const int gy0 = py0 - 4, gx0 = px0 - 7;
    const float* inb = in + (size_t)bz * H * W;
    for (int i = tid; i < TILE_ROWS * TILE_COLS; i += 256) {
        int r = i / TILE_COLS, c = i - r * TILE_COLS;
        int gy = gy0 + r, gx = gx0 + c;
        float v = 0.0f;
        if (gy >= 0 && gy < H && gx >= 0 && gx < W) v = inb[gy * W + gx];
        unsigned key = (unsigned)(v * KSCALE);
        key = min(key, 30719u) + (unsigned)KBIAS;
        keytile[r * TILE_W + c] = (unsigned short)key;
    }
    __syncthreads();

    const bool border = (blockIdx.x == 0) | (blockIdx.x == gridDim.x - 1) |
                        (blockIdx.y == 0) | (blockIdx.y == gridDim.y - 1);

    const int py = py0 + wrp;
    const float centerf = inb[py * W + px0 + lane];

    const int o0 = offs[lane];
    const int o1 = offs[lane + 32];
    const int o2 = offs[lane + 64];
    const int o3 = (lane < 30) ? (int)offs[lane + 96] : 0;
    const bool has3 = (lane < 30);

    const unsigned short* rowp = &keytile[(wrp + 4) * TILE_W + 7];
    float myscale = 0.0f;

    if (!border) {
        #pragma unroll 1
        for (int i = 0; i < 16; ++i) {
            const unsigned short* p = rowp + 2 * i;
            unsigned pk0 = (unsigned)p[o0] | ((unsigned)p[o0 + 1] << 16);
            unsigned pk1 = (unsigned)p[o1] | ((unsigned)p[o1 + 1] << 16);
            unsigned pk2 = (unsigned)p[o2] | ((unsigned)p[o2 + 1] << 16);
            unsigned pk3 = has3 ? ((unsigned)p[o3] | ((unsigned)p[o3 + 1] << 16)) : SENT2;
            float scP, scQ;
            process_pair<5>(pk0, pk1, pk2, pk3, scP, scQ);
            if (lane == 2 * i)     myscale = scP;
            if (lane == 2 * i + 1) myscale = scQ;
        }
    } else {
        #pragma unroll 1
        for (int i = 0; i < 16; ++i) {
            const unsigned short* p = rowp + 2 * i;
            unsigned pk0 = (unsigned)p[o0] | ((unsigned)p[o0 + 1] << 16);
            unsigned pk1 = (unsigned)p[o1] | ((unsigned)p[o1 + 1] << 16);
            unsigned pk2 = (unsigned)p[o2] | ((unsigned)p[o2 + 1] << 16);
            unsigned pk3 = has3 ? ((unsigned)p[o3] | ((unsigned)p[o3 + 1] << 16)) : SENT2;
            float scP, scQ;
            process_pair<0>(pk0, pk1, pk2, pk3, scP, scQ);   // exact at borders
            if (lane == 2 * i)     myscale = scP;
            if (lane == 2 * i + 1) myscale = scQ;
        }
    }

    out[(size_t)bz * H * W + py * W + px0 + lane] = centerf * myscale;
}

extern "C" void kernel_launch(void* const* d_in, const int* in_sizes, int n_in,
                              void* d_out, int out_size)
{
    const float* in = (const float*)d_in[0];
    float* out = (float*)d_out;
    const int H = 512, W = 512;
    const int B = in_sizes[0] / (H * W);

    dim3 grid(W / 32, H / 8, B);
    dim3 block(256);
    tmcfar_kernel<<<grid, block>>>(in, out, H, W);
}

// round 4
// speedup vs baseline: 2.4232x; 1.1194x over previous
#include <cuda_runtime.h>
#include <cuda_fp16.h>
#include <cstdint>

// TM-CFAR: out = rd_map / trimmed_mean(sorted 126 reference cells, ranks [31,94))
// Window 9x15, guard 3x3, zero padding.
//
// Round-4: warp per 2 pixels.
//  - packed u32 key tile: entry c = (key[c] | key[c+1]<<16)  -> 1 LDS.32/word
//  - interior: 32-bin shared histogram (key>>10) + SHFL-scan locates the
//    1024-wide bucket for ranks 30 & 94 (replaces bisect bits 14..10)
//  - 4 fp16-SIMD bisection steps (bits 9..6), midpoint substitution at 64-wide
//  - border blocks: exact full bisection bits 14..0 (zero-padding ties)

#define TILE_WP   80      // packed tile stride in u32 (80 % 32 == 16: bank spread)
#define TILE_COLS 46
#define TILE_ROWS 16
#define KBIAS     1024
#define KSCALE    30720.0f
#define SENT2     0x7BFF7BFFu   // max-finite fp16: never below any threshold, hmul-safe

static __device__ __forceinline__ unsigned h2u(__half2 h) { return *reinterpret_cast<unsigned*>(&h); }
static __device__ __forceinline__ __half2  u2h(unsigned u) { return *reinterpret_cast<__half2*>(&u); }

template <int STARTBIT, int STOPBIT>
static __device__ __forceinline__ void bisect_pair(
    unsigned pk0, unsigned pk1, unsigned pk2, unsigned pk3,
    unsigned A2, unsigned B2,
    float& scP, float& scQ)
{
    const __half2 magic = u2h(0x64006400u);   // (1024.0, 1024.0)

    #pragma unroll
    for (int bit = STARTBIT; bit >= STOPBIT; --bit) {
        const unsigned step2 = (1u << bit) * 0x10001u;
        const __half2 mA = u2h(A2 + step2);
        const __half2 mB = u2h(B2 + step2);

        __half2 sA = __hadd2(__hadd2(__hlt2(u2h(pk0), mA), __hlt2(u2h(pk1), mA)),
                             __hadd2(__hlt2(u2h(pk2), mA), __hlt2(u2h(pk3), mA)));
        __half2 sB = __hadd2(__hadd2(__hlt2(u2h(pk0), mB), __hlt2(u2h(pk1), mB)),
                             __hadd2(__hlt2(u2h(pk2), mB), __hlt2(u2h(pk3), mB)));
        const unsigned Ar = h2u(__hadd2(sA, magic));   // bytes (cAP, 0x64, cAQ, 0x64)
        const unsigned Br = h2u(__hadd2(sB, magic));
        unsigned cc = __byte_perm(Ar, Br, 0x6420);     // (cAP, cAQ, cBP, cBQ)
        cc = __reduce_add_sync(0xffffffffu, cc);

        // byte-wise accept flags: bytes 0,1 vs 30 ; bytes 2,3 vs 94
        const unsigned f = ((0xDEDE9E9Eu - cc) >> 7) & 0x01010101u;
        A2 += __byte_perm(f, 0, 0x4140) << bit;   // (fAP | fAQ<<16) << bit
        B2 += __byte_perm(f, 0, 0x4342) << bit;
    }

    const int MIDOFF = (STOPBIT > 0) ? (1 << (STOPBIT - 1)) : 0;

    // ---- epilogue: exact counts below brackets + masked range sums ----
    const __half2 hA = u2h(A2), hB = u2h(B2);
    const __half2 lA0 = __hlt2(u2h(pk0), hA), lA1 = __hlt2(u2h(pk1), hA);
    const __half2 lA2v = __hlt2(u2h(pk2), hA), lA3 = __hlt2(u2h(pk3), hA);
    const __half2 lB0 = __hlt2(u2h(pk0), hB), lB1 = __hlt2(u2h(pk1), hB);
    const __half2 lB2v = __hlt2(u2h(pk2), hB), lB3 = __hlt2(u2h(pk3), hB);

    const unsigned in0 = h2u(lB0) & ~h2u(lA0);
    const unsigned in1 = h2u(lB1) & ~h2u(lA1);
    const unsigned in2 = h2u(lB2v) & ~h2u(lA2v);
    const unsigned in3 = h2u(lB3) & ~h2u(lA3);

    const unsigned km0 = h2u(__hmul2(u2h(pk0), u2h(in0)));
    const unsigned km1 = h2u(__hmul2(u2h(pk1), u2h(in1)));
    const unsigned km2 = h2u(__hmul2(u2h(pk2), u2h(in2)));
    const unsigned km3 = h2u(__hmul2(u2h(pk3), u2h(in3)));

    unsigned sP = (km0 & 0xFFFFu) + (km1 & 0xFFFFu) + (km2 & 0xFFFFu) + (km3 & 0xFFFFu);
    unsigned sQ = (km0 >> 16) + (km1 >> 16) + (km2 >> 16) + (km3 >> 16);

    const __half2 cA2 = __hadd2(__hadd2(lA0, lA1), __hadd2(lA2v, lA3));
    const __half2 cB2 = __hadd2(__hadd2(lB0, lB1), __hadd2(lB2v, lB3));
    unsigned ccf = __byte_perm(h2u(__hadd2(cA2, magic)), h2u(__hadd2(cB2, magic)), 0x6420);

    ccf = __reduce_add_sync(0xffffffffu, ccf);
    sP  = __reduce_add_sync(0xffffffffu, sP);
    sQ  = __reduce_add_sync(0xffffffffu, sQ);

    const int cAP = (int)(ccf & 255u);
    const int cAQ = (int)((ccf >> 8) & 255u);
    const int cBP = (int)((ccf >> 16) & 255u);
    const int cBQ = (int)(ccf >> 24);

    const int TAP = (int)(A2 & 0xFFFFu) + MIDOFF, TAQ = (int)(A2 >> 16) + MIDOFF;
    const int TBP = (int)(B2 & 0xFFFFu) + MIDOFF, TBQ = (int)(B2 >> 16) + MIDOFF;

    const int keptP = (int)sP - KBIAS * (cBP - cAP)
                    + (94 - cBP) * (TBP - KBIAS) - (31 - cAP) * (TAP - KBIAS);
    const int keptQ = (int)sQ - KBIAS * (cBQ - cAQ)
                    + (94 - cBQ) * (TBQ - KBIAS) - (31 - cAQ) * (TAQ - KBIAS);

    scP = __fdividef(63.0f * KSCALE, (float)keptP);
    scQ = __fdividef(63.0f * KSCALE, (float)keptQ);
}

__global__ __launch_bounds__(256, 6)
void tmcfar_kernel(const float* __restrict__ in, float* __restrict__ out,
                   int H, int W)
{
    __shared__ unsigned keypack[TILE_ROWS * TILE_WP];   // 5120 B
    __shared__ int      offs[128];                       // u32-element offsets
    __shared__ unsigned hist[8][64];                     // per-warp: P bins 0..31, Q bins 32..63

    const int tid  = threadIdx.x;
    const int lane = tid & 31;
    const int wrp  = tid >> 5;
    const int bz   = blockIdx.z;
    const int py0  = blockIdx.y * 8;
    const int px0  = blockIdx.x * 32;

    // compacted (dy,dx) offsets of the 126 reference cells (u32-element units)
    if (tid < 135) {
        int r = tid / 15, c = tid - r * 15;
        bool guard = (r >= 3 && r <= 5 && c >= 6 && c <= 8);
        if (!guard) {
            int rowsBefore = min(max(r - 3, 0), 3);
            int sameRow    = (r >= 3 && r <= 5) ? min(max(c - 6, 0), 3) : 0;
            int gb = 3 * rowsBefore + sameRow;
            offs[tid - gb] = (r - 4) * TILE_WP + (c - 7);
        }
    }

    // load + quantize directly into packed tile: entry c = key[c] | key[c+1]<<16
    const int gy0 = py0 - 4, gx0 = px0 - 7;
    const float* inb = in + (size_t)bz * H * W;
    for (int idx = tid; idx < TILE_ROWS * 64; idx += 256) {
        int r = idx >> 6, c = idx & 63;
        if (c < TILE_COLS - 1) {
            int gy = gy0 + r, gx = gx0 + c;
            bool okr = (gy >= 0 && gy < H);
            float v0 = (okr && gx >= 0     && gx < W)     ? inb[gy * W + gx]     : 0.0f;
            float v1 = (okr && gx + 1 >= 0 && gx + 1 < W) ? inb[gy * W + gx + 1] : 0.0f;
            unsigned k0 = min((unsigned)(v0 * KSCALE), 30719u) + (unsigned)KBIAS;
            unsigned k1 = min((unsigned)(v1 * KSCALE), 30719u) + (unsigned)KBIAS;
            keypack[r * TILE_WP + c] = k0 | (k1 << 16);
        }
    }
    __syncthreads();

    const bool border = (blockIdx.x == 0) | (blockIdx.x == gridDim.x - 1) |
                        (blockIdx.y == 0) | (blockIdx.y == gridDim.y - 1);

    const int py = py0 + wrp;
    const float centerf = inb[py * W + px0 + lane];

    const int o0 = offs[lane];
    const int o1 = offs[lane + 32];
    const int o2 = offs[lane + 64];
    const int o3 = (lane < 30) ? offs[lane + 96] : 0;
    const bool has3 = (lane < 30);

    const unsigned* basep = &keypack[(wrp + 4) * TILE_WP + 7];
    unsigned* hP = &hist[wrp][0];
    unsigned* hQ = &hist[wrp][32];
    float myscale = 0.0f;

    if (!border) {
        #pragma unroll 1
        for (int i = 0; i < 16; ++i) {
            const unsigned* p = basep + 2 * i;
            const unsigned pk0 = p[o0];
            const unsigned pk1 = p[o1];
            const unsigned pk2 = p[o2];
            const unsigned pk3 = has3 ? p[o3] : SENT2;

            // ---- 32-bin coarse histogram (bins = key >> 10) ----
            hP[lane] = 0; hQ[lane] = 0;
            __syncwarp();
            atomicAdd(&hP[(pk0 >> 10) & 31], 1u);  atomicAdd(&hQ[pk0 >> 26], 1u);
            atomicAdd(&hP[(pk1 >> 10) & 31], 1u);  atomicAdd(&hQ[pk1 >> 26], 1u);
            atomicAdd(&hP[(pk2 >> 10) & 31], 1u);  atomicAdd(&hQ[pk2 >> 26], 1u);
            if (has3) {
                atomicAdd(&hP[(pk3 >> 10) & 31], 1u);
                atomicAdd(&hQ[pk3 >> 26], 1u);
            }
            __syncwarp();

            // ---- inclusive scan + bucket location for ranks 30 and 94 ----
            unsigned cP = hP[lane], cQ = hQ[lane];
            #pragma unroll
            for (int d = 1; d < 32; d <<= 1) {
                unsigned tP = __shfl_up_sync(0xffffffffu, cP, d);
                unsigned tQ = __shfl_up_sync(0xffffffffu, cQ, d);
                if (lane >= d) { cP += tP; cQ += tQ; }
            }
            const unsigned bAP = (unsigned)(__ffs(__ballot_sync(0xffffffffu, cP > 30u)) - 1);
            const unsigned bBP = (unsigned)(__ffs(__ballot_sync(0xffffffffu, cP > 94u)) - 1);
            const unsigned bAQ = (unsigned)(__ffs(__ballot_sync(0xffffffffu, cQ > 30u)) - 1);
            const unsigned bBQ = (unsigned)(__ffs(__ballot_sync(0xffffffffu, cQ > 94u)) - 1);

            const unsigned A2 = (bAP << 10) | (bAQ << 26);
            const unsigned B2 = (bBP << 10) | (bBQ << 26);

            float scP, scQ;
            bisect_pair<9, 6>(pk0, pk1, pk2, pk3, A2, B2, scP, scQ);
            if (lane == 2 * i)     myscale = scP;
            if (lane == 2 * i + 1) myscale = scQ;
        }
    } else {
        #pragma unroll 1
        for (int i = 0; i < 16; ++i) {
            const unsigned* p = basep + 2 * i;
            const unsigned pk0 = p[o0];
            const unsigned pk1 = p[o1];
            const unsigned pk2 = p[o2];
            const unsigned pk3 = has3 ? p[o3] : SENT2;

            float scP, scQ;
            bisect_pair<14, 0>(pk0, pk1, pk2, pk3, 0x04000400u, 0x04000400u, scP, scQ);
            if (lane == 2 * i)     myscale = scP;
            if (lane == 2 * i + 1) myscale = scQ;
        }
    }

    out[(size_t)bz * H * W + py * W + px0 + lane] = centerf * myscale;
}

extern "C" void kernel_launch(void* const* d_in, const int* in_sizes, int n_in,
                              void* d_out, int out_size)
{
    const float* in = (const float*)d_in[0];
    float* out = (float*)d_out;
    const int H = 512, W = 512;
    const int B = in_sizes[0] / (H * W);

    dim3 grid(W / 32, H / 8, B);
    dim3 block(256);
    tmcfar_kernel<<<grid, block>>>(in, out, H, W);
}

// round 5
// speedup vs baseline: 2.6675x; 1.1008x over previous
#include <cuda_runtime.h>
#include <cuda_fp16.h>
#include <cstdint>

// TM-CFAR: out = rd_map / trimmed_mean(sorted 126 reference cells, ranks [31,94))
// Window 9x15, guard 3x3, zero padding.
//
// Round-5: warp per 2 pixels.
//  - packed u32 key tile: entry c = (key[c] | key[c+1]<<16)  -> 1 LDS.32/word
//  - interior: ONE packed 32-bin histogram (P in halfword0, Q in halfword1),
//    single SHFL-scan chain, ballots locate the 1024-wide buckets for ranks 30/94
//  - 3 fp16-SIMD bisection steps (bits 9..7), midpoint substitution at 128-wide
//  - border blocks: exact full bisection bits 14..0 (zero-padding ties)

#define TILE_WP   80      // packed tile stride in u32 (80 % 32 == 16: bank spread)
#define TILE_COLS 46
#define TILE_ROWS 16
#define KBIAS     1024
#define KSCALE    30720.0f
#define SENT2     0x7BFF7BFFu   // max-finite fp16: never below any threshold, hmul-safe

static __device__ __forceinline__ unsigned h2u(__half2 h) { return *reinterpret_cast<unsigned*>(&h); }
static __device__ __forceinline__ __half2  u2h(unsigned u) { return *reinterpret_cast<__half2*>(&u); }

template <int STARTBIT, int STOPBIT>
static __device__ __forceinline__ void bisect_pair(
    unsigned pk0, unsigned pk1, unsigned pk2, unsigned pk3,
    unsigned A2, unsigned B2,
    float& scP, float& scQ)
{
    const __half2 magic = u2h(0x64006400u);   // (1024.0, 1024.0)

    #pragma unroll
    for (int bit = STARTBIT; bit >= STOPBIT; --bit) {
        const unsigned step2 = (1u << bit) * 0x10001u;
        const __half2 mA = u2h(A2 + step2);
        const __half2 mB = u2h(B2 + step2);

        __half2 sA = __hadd2(__hadd2(__hlt2(u2h(pk0), mA), __hlt2(u2h(pk1), mA)),
                             __hadd2(__hlt2(u2h(pk2), mA), __hlt2(u2h(pk3), mA)));
        __half2 sB = __hadd2(__hadd2(__hlt2(u2h(pk0), mB), __hlt2(u2h(pk1), mB)),
                             __hadd2(__hlt2(u2h(pk2), mB), __hlt2(u2h(pk3), mB)));
        const unsigned Ar = h2u(__hadd2(sA, magic));   // bytes (cAP, 0x64, cAQ, 0x64)
        const unsigned Br = h2u(__hadd2(sB, magic));
        unsigned cc = __byte_perm(Ar, Br, 0x6420);     // (cAP, cAQ, cBP, cBQ)
        cc = __reduce_add_sync(0xffffffffu, cc);

        // byte-wise accept flags: bytes 0,1 vs 30 ; bytes 2,3 vs 94
        const unsigned f = ((0xDEDE9E9Eu - cc) >> 7) & 0x01010101u;
        A2 += __byte_perm(f, 0, 0x4140) << bit;   // (fAP | fAQ<<16) << bit
        B2 += __byte_perm(f, 0, 0x4342) << bit;
    }

    const int MIDOFF = (STOPBIT > 0) ? (1 << (STOPBIT - 1)) : 0;

    // ---- epilogue: exact counts below brackets + masked range sums ----
    const __half2 hA = u2h(A2), hB = u2h(B2);
    const __half2 lA0 = __hlt2(u2h(pk0), hA), lA1 = __hlt2(u2h(pk1), hA);
    const __half2 lA2v = __hlt2(u2h(pk2), hA), lA3 = __hlt2(u2h(pk3), hA);
    const __half2 lB0 = __hlt2(u2h(pk0), hB), lB1 = __hlt2(u2h(pk1), hB);
    const __half2 lB2v = __hlt2(u2h(pk2), hB), lB3 = __hlt2(u2h(pk3), hB);

    const unsigned in0 = h2u(lB0) & ~h2u(lA0);
    const unsigned in1 = h2u(lB1) & ~h2u(lA1);
    const unsigned in2 = h2u(lB2v) & ~h2u(lA2v);
    const unsigned in3 = h2u(lB3) & ~h2u(lA3);

    const unsigned km0 = h2u(__hmul2(u2h(pk0), u2h(in0)));
    const unsigned km1 = h2u(__hmul2(u2h(pk1), u2h(in1)));
    const unsigned km2 = h2u(__hmul2(u2h(pk2), u2h(in2)));
    const unsigned km3 = h2u(__hmul2(u2h(pk3), u2h(in3)));

    // halfword-pair pack + SIMD add (lanes <= 2*31743, no carry)
    const unsigned lo01 = __byte_perm(km0, km1, 0x5410);
    const unsigned lo23 = __byte_perm(km2, km3, 0x5410);
    const unsigned hi01 = __byte_perm(km0, km1, 0x7632);
    const unsigned hi23 = __byte_perm(km2, km3, 0x7632);
    const unsigned vlo = __vadd2(lo01, lo23);
    const unsigned vhi = __vadd2(hi01, hi23);
    unsigned sP = (vlo & 0xFFFFu) + (vlo >> 16);
    unsigned sQ = (vhi & 0xFFFFu) + (vhi >> 16);

    const __half2 cA2 = __hadd2(__hadd2(lA0, lA1), __hadd2(lA2v, lA3));
    const __half2 cB2 = __hadd2(__hadd2(lB0, lB1), __hadd2(lB2v, lB3));
    unsigned ccf = __byte_perm(h2u(__hadd2(cA2, magic)), h2u(__hadd2(cB2, magic)), 0x6420);

    ccf = __reduce_add_sync(0xffffffffu, ccf);
    sP  = __reduce_add_sync(0xffffffffu, sP);
    sQ  = __reduce_add_sync(0xffffffffu, sQ);

    const int cAP = (int)(ccf & 255u);
    const int cAQ = (int)((ccf >> 8) & 255u);
    const int cBP = (int)((ccf >> 16) & 255u);
    const int cBQ = (int)(ccf >> 24);

    const int TAP = (int)(A2 & 0xFFFFu) + MIDOFF, TAQ = (int)(A2 >> 16) + MIDOFF;
    const int TBP = (int)(B2 & 0xFFFFu) + MIDOFF, TBQ = (int)(B2 >> 16) + MIDOFF;

    const int keptP = (int)sP - KBIAS * (cBP - cAP)
                    + (94 - cBP) * (TBP - KBIAS) - (31 - cAP) * (TAP - KBIAS);
    const int keptQ = (int)sQ - KBIAS * (cBQ - cAQ)
                    + (94 - cBQ) * (TBQ - KBIAS) - (31 - cAQ) * (TAQ - KBIAS);

    scP = __fdividef(63.0f * KSCALE, (float)keptP);
    scQ = __fdividef(63.0f * KSCALE, (float)keptQ);
}

__global__ __launch_bounds__(256, 7)
void tmcfar_kernel(const float* __restrict__ in, float* __restrict__ out,
                   int H, int W)
{
    __shared__ unsigned keypack[TILE_ROWS * TILE_WP];   // 5120 B
    __shared__ int      offs[128];                      // u32-element offsets
    __shared__ unsigned hist[8][32];                    // per-warp packed: P=hw0, Q=hw1

    const int tid  = threadIdx.x;
    const int lane = tid & 31;
    const int wrp  = tid >> 5;
    const int bz   = blockIdx.z;
    const int py0  = blockIdx.y * 8;
    const int px0  = blockIdx.x * 32;

    // compacted (dy,dx) offsets of the 126 reference cells (u32-element units)
    if (tid < 135) {
        int r = tid / 15, c = tid - r * 15;
        bool guard = (r >= 3 && r <= 5 && c >= 6 && c <= 8);
        if (!guard) {
            int rowsBefore = min(max(r - 3, 0), 3);
            int sameRow    = (r >= 3 && r <= 5) ? min(max(c - 6, 0), 3) : 0;
            int gb = 3 * rowsBefore + sameRow;
            offs[tid - gb] = (r - 4) * TILE_WP + (c - 7);
        }
    }

    // load + quantize directly into packed tile: entry c = key[c] | key[c+1]<<16
    const int gy0 = py0 - 4, gx0 = px0 - 7;
    const float* inb = in + (size_t)bz * H * W;
    for (int idx = tid; idx < TILE_ROWS * 64; idx += 256) {
        int r = idx >> 6, c = idx & 63;
        if (c < TILE_COLS - 1) {
            int gy = gy0 + r, gx = gx0 + c;
            bool okr = (gy >= 0 && gy < H);
            float v0 = (okr && gx >= 0     && gx < W)     ? inb[gy * W + gx]     : 0.0f;
            float v1 = (okr && gx + 1 >= 0 && gx + 1 < W) ? inb[gy * W + gx + 1] : 0.0f;
            unsigned k0 = min((unsigned)(v0 * KSCALE), 30719u) + (unsigned)KBIAS;
            unsigned k1 = min((unsigned)(v1 * KSCALE), 30719u) + (unsigned)KBIAS;
            keypack[r * TILE_WP + c] = k0 | (k1 << 16);
        }
    }
    __syncthreads();

    const bool border = (blockIdx.x == 0) | (blockIdx.x == gridDim.x - 1) |
                        (blockIdx.y == 0) | (blockIdx.y == gridDim.y - 1);

    const int py = py0 + wrp;
    const float centerf = inb[py * W + px0 + lane];

    const int o0 = offs[lane];
    const int o1 = offs[lane + 32];
    const int o2 = offs[lane + 64];
    const int o3 = (lane < 30) ? offs[lane + 96] : 0;
    const bool has3 = (lane < 30);

    const unsigned* basep = &keypack[(wrp + 4) * TILE_WP + 7];
    unsigned* hst = &hist[wrp][0];
    float myscale = 0.0f;

    if (!border) {
        #pragma unroll 1
        for (int i = 0; i < 16; ++i) {
            const unsigned* p = basep + 2 * i;
            const unsigned pk0 = p[o0];
            const unsigned pk1 = p[o1];
            const unsigned pk2 = p[o2];
            const unsigned pk3 = has3 ? p[o3] : SENT2;

            // ---- packed 32-bin coarse histogram (bin = key >> 10) ----
            hst[lane] = 0;
            __syncwarp();
            atomicAdd(&hst[(pk0 >> 10) & 31], 1u);  atomicAdd(&hst[pk0 >> 26], 0x10000u);
            atomicAdd(&hst[(pk1 >> 10) & 31], 1u);  atomicAdd(&hst[pk1 >> 26], 0x10000u);
            atomicAdd(&hst[(pk2 >> 10) & 31], 1u);  atomicAdd(&hst[pk2 >> 26], 0x10000u);
            if (has3) {
                atomicAdd(&hst[(pk3 >> 10) & 31], 1u);
                atomicAdd(&hst[pk3 >> 26], 0x10000u);
            }
            __syncwarp();

            // ---- single packed inclusive scan (P in hw0, Q in hw1) ----
            unsigned c = hst[lane];
            #pragma unroll
            for (int d = 1; d < 32; d <<= 1) {
                unsigned t = __shfl_up_sync(0xffffffffu, c, d);
                if (lane >= d) c += t;
            }
            const unsigned cP = c & 0xFFFFu, cQ = c >> 16;
            const unsigned bAP = (unsigned)(__ffs(__ballot_sync(0xffffffffu, cP > 30u)) - 1);
            const unsigned bBP = (unsigned)(__ffs(__ballot_sync(0xffffffffu, cP > 94u)) - 1);
            const unsigned bAQ = (unsigned)(__ffs(__ballot_sync(0xffffffffu, cQ > 30u)) - 1);
            const unsigned bBQ = (unsigned)(__ffs(__ballot_sync(0xffffffffu, cQ > 94u)) - 1);

            const unsigned A2 = (bAP << 10) | (bAQ << 26);
            const unsigned B2 = (bBP << 10) | (bBQ << 26);

            float scP, scQ;
            bisect_pair<9, 7>(pk0, pk1, pk2, pk3, A2, B2, scP, scQ);
            if (lane == 2 * i)     myscale = scP;
            if (lane == 2 * i + 1) myscale = scQ;
        }
    } else {
        #pragma unroll 1
        for (int i = 0; i < 16; ++i) {
            const unsigned* p = basep + 2 * i;
            const unsigned pk0 = p[o0];
            const unsigned pk1 = p[o1];
            const unsigned pk2 = p[o2];
            const unsigned pk3 = has3 ? p[o3] : SENT2;

            float scP, scQ;
            bisect_pair<14, 0>(pk0, pk1, pk2, pk3, 0x04000400u, 0x04000400u, scP, scQ);
            if (lane == 2 * i)     myscale = scP;
            if (lane == 2 * i + 1) myscale = scQ;
        }
    }

    out[(size_t)bz * H * W + py * W + px0 + lane] = centerf * myscale;
}

extern "C" void kernel_launch(void* const* d_in, const int* in_sizes, int n_in,
                              void* d_out, int out_size)
{
    const float* in = (const float*)d_in[0];
    float* out = (float*)d_out;
    const int H = 512, W = 512;
    const int B = in_sizes[0] / (H * W);

    dim3 grid(W / 32, H / 8, B);
    dim3 block(256);
    tmcfar_kernel<<<grid, block>>>(in, out, H, W);
}

// round 6
// speedup vs baseline: 2.9704x; 1.1135x over previous
#include <cuda_runtime.h>
#include <cuda_fp16.h>
#include <cstdint>

// TM-CFAR: out = rd_map / trimmed_mean(sorted 126 reference cells, ranks [31,94))
// Window 9x15, guard 3x3, zero padding.
//
// Round-6: warp per 2 pixels.
//  - packed u32 key tile: entry c = (key[c] | key[c+1]<<16)
//  - interior: 128-bin packed histogram (bin = key>>8, P=hw0/Q=hw1) located via
//    uint4 ld + lane-serial prefix + one packed warp scan + byte-SIMD popc
//    bucket search (ONE REDUX) -> 256-wide bracket
//  - ONE fp16-SIMD bisection step (bit 7), midpoint substitution at 128-wide
//  - border blocks: exact full bisection bits 14..0 (zero-padding ties)

#define TILE_WP   80      // packed tile stride in u32 (80 % 32 == 16: bank spread)
#define TILE_COLS 46
#define TILE_ROWS 16
#define KBIAS     1024
#define KSCALE    30720.0f
#define SENT2     0x7BFF7BFFu   // max-finite fp16: never below any threshold, hmul-safe

static __device__ __forceinline__ unsigned h2u(__half2 h) { return *reinterpret_cast<unsigned*>(&h); }
static __device__ __forceinline__ __half2  u2h(unsigned u) { return *reinterpret_cast<__half2*>(&u); }

template <int STARTBIT, int STOPBIT>
static __device__ __forceinline__ void bisect_pair(
    unsigned pk0, unsigned pk1, unsigned pk2, unsigned pk3,
    unsigned A2, unsigned B2,
    float& scP, float& scQ)
{
    const __half2 magic = u2h(0x64006400u);   // (1024.0, 1024.0)

    #pragma unroll
    for (int bit = STARTBIT; bit >= STOPBIT; --bit) {
        const unsigned step2 = (1u << bit) * 0x10001u;
        const __half2 mA = u2h(A2 + step2);
        const __half2 mB = u2h(B2 + step2);

        __half2 sA = __hadd2(__hadd2(__hlt2(u2h(pk0), mA), __hlt2(u2h(pk1), mA)),
                             __hadd2(__hlt2(u2h(pk2), mA), __hlt2(u2h(pk3), mA)));
        __half2 sB = __hadd2(__hadd2(__hlt2(u2h(pk0), mB), __hlt2(u2h(pk1), mB)),
                             __hadd2(__hlt2(u2h(pk2), mB), __hlt2(u2h(pk3), mB)));
        const unsigned Ar = h2u(__hadd2(sA, magic));   // bytes (cAP, 0x64, cAQ, 0x64)
        const unsigned Br = h2u(__hadd2(sB, magic));
        unsigned cc = __byte_perm(Ar, Br, 0x6420);     // (cAP, cAQ, cBP, cBQ)
        cc = __reduce_add_sync(0xffffffffu, cc);

        // byte-wise accept flags: bytes 0,1 vs 30 ; bytes 2,3 vs 94
        const unsigned f = ((0xDEDE9E9Eu - cc) >> 7) & 0x01010101u;
        A2 += __byte_perm(f, 0, 0x4140) << bit;   // (fAP | fAQ<<16) << bit
        B2 += __byte_perm(f, 0, 0x4342) << bit;
    }

    const int MIDOFF = (STOPBIT > 0) ? (1 << (STOPBIT - 1)) : 0;

    // ---- epilogue: exact counts below brackets + masked range sums ----
    const __half2 hA = u2h(A2), hB = u2h(B2);
    const __half2 lA0 = __hlt2(u2h(pk0), hA), lA1 = __hlt2(u2h(pk1), hA);
    const __half2 lA2v = __hlt2(u2h(pk2), hA), lA3 = __hlt2(u2h(pk3), hA);
    const __half2 lB0 = __hlt2(u2h(pk0), hB), lB1 = __hlt2(u2h(pk1), hB);
    const __half2 lB2v = __hlt2(u2h(pk2), hB), lB3 = __hlt2(u2h(pk3), hB);

    const unsigned in0 = h2u(lB0) & ~h2u(lA0);
    const unsigned in1 = h2u(lB1) & ~h2u(lA1);
    const unsigned in2 = h2u(lB2v) & ~h2u(lA2v);
    const unsigned in3 = h2u(lB3) & ~h2u(lA3);

    const unsigned km0 = h2u(__hmul2(u2h(pk0), u2h(in0)));
    const unsigned km1 = h2u(__hmul2(u2h(pk1), u2h(in1)));
    const unsigned km2 = h2u(__hmul2(u2h(pk2), u2h(in2)));
    const unsigned km3 = h2u(__hmul2(u2h(pk3), u2h(in3)));

    // halfword-pair pack + SIMD add (lanes <= 2*31743, no carry)
    const unsigned lo01 = __byte_perm(km0, km1, 0x5410);
    const unsigned lo23 = __byte_perm(km2, km3, 0x5410);
    const unsigned hi01 = __byte_perm(km0, km1, 0x7632);
    const unsigned hi23 = __byte_perm(km2, km3, 0x7632);
    const unsigned vlo = __vadd2(lo01, lo23);
    const unsigned vhi = __vadd2(hi01, hi23);
    unsigned sP = (vlo & 0xFFFFu) + (vlo >> 16);
    unsigned sQ = (vhi & 0xFFFFu) + (vhi >> 16);

    const __half2 cA2 = __hadd2(__hadd2(lA0, lA1), __hadd2(lA2v, lA3));
    const __half2 cB2 = __hadd2(__hadd2(lB0, lB1), __hadd2(lB2v, lB3));
    unsigned ccf = __byte_perm(h2u(__hadd2(cA2, magic)), h2u(__hadd2(cB2, magic)), 0x6420);

    ccf = __reduce_add_sync(0xffffffffu, ccf);
    sP  = __reduce_add_sync(0xffffffffu, sP);
    sQ  = __reduce_add_sync(0xffffffffu, sQ);

    const int cAP = (int)(ccf & 255u);
    const int cAQ = (int)((ccf >> 8) & 255u);
    const int cBP = (int)((ccf >> 16) & 255u);
    const int cBQ = (int)(ccf >> 24);

    const int TAP = (int)(A2 & 0xFFFFu) + MIDOFF, TAQ = (int)(A2 >> 16) + MIDOFF;
    const int TBP = (int)(B2 & 0xFFFFu) + MIDOFF, TBQ = (int)(B2 >> 16) + MIDOFF;

    const int keptP = (int)sP - KBIAS * (cBP - cAP)
                    + (94 - cBP) * (TBP - KBIAS) - (31 - cAP) * (TAP - KBIAS);
    const int keptQ = (int)sQ - KBIAS * (cBQ - cAQ)
                    + (94 - cBQ) * (TBQ - KBIAS) - (31 - cAQ) * (TAQ - KBIAS);

    scP = __fdividef(63.0f * KSCALE, (float)keptP);
    scQ = __fdividef(63.0f * KSCALE, (float)keptQ);
}

__global__ __launch_bounds__(256, 7)
void tmcfar_kernel(const float* __restrict__ in, float* __restrict__ out,
                   int H, int W)
{
    __shared__ unsigned keypack[TILE_ROWS * TILE_WP];        // 5120 B
    __shared__ int      offs[128];                           // u32-element offsets
    __shared__ __align__(16) unsigned hist[8][128];          // 128 bins, P=hw0 Q=hw1

    const int tid  = threadIdx.x;
    const int lane = tid & 31;
    const int wrp  = tid >> 5;
    const int bz   = blockIdx.z;
    const int py0  = blockIdx.y * 8;
    const int px0  = blockIdx.x * 32;

    // compacted (dy,dx) offsets of the 126 reference cells (u32-element units)
    if (tid < 135) {
        int r = tid / 15, c = tid - r * 15;
        bool guard = (r >= 3 && r <= 5 && c >= 6 && c <= 8);
        if (!guard) {
            int rowsBefore = min(max(r - 3, 0), 3);
            int sameRow    = (r >= 3 && r <= 5) ? min(max(c - 6, 0), 3) : 0;
            int gb = 3 * rowsBefore + sameRow;
            offs[tid - gb] = (r - 4) * TILE_WP + (c - 7);
        }
    }

    // load + quantize directly into packed tile: entry c = key[c] | key[c+1]<<16
    const int gy0 = py0 - 4, gx0 = px0 - 7;
    const float* inb = in + (size_t)bz * H * W;
    for (int idx = tid; idx < TILE_ROWS * 64; idx += 256) {
        int r = idx >> 6, c = idx & 63;
        if (c < TILE_COLS - 1) {
            int gy = gy0 + r, gx = gx0 + c;
            bool okr = (gy >= 0 && gy < H);
            float v0 = (okr && gx >= 0     && gx < W)     ? inb[gy * W + gx]     : 0.0f;
            float v1 = (okr && gx + 1 >= 0 && gx + 1 < W) ? inb[gy * W + gx + 1] : 0.0f;
            unsigned k0 = min((unsigned)(v0 * KSCALE), 30719u) + (unsigned)KBIAS;
            unsigned k1 = min((unsigned)(v1 * KSCALE), 30719u) + (unsigned)KBIAS;
            keypack[r * TILE_WP + c] = k0 | (k1 << 16);
        }
    }
    __syncthreads();

    const bool border = (blockIdx.x == 0) | (blockIdx.x == gridDim.x - 1) |
                        (blockIdx.y == 0) | (blockIdx.y == gridDim.y - 1);

    const int py = py0 + wrp;
    const float centerf = inb[py * W + px0 + lane];

    const int o0 = offs[lane];
    const int o1 = offs[lane + 32];
    const int o2 = offs[lane + 64];
    const int o3 = (lane < 30) ? offs[lane + 96] : 0;
    const bool has3 = (lane < 30);

    const unsigned* basep = &keypack[(wrp + 4) * TILE_WP + 7];
    unsigned* hst = &hist[wrp][0];
    float myscale = 0.0f;

    if (!border) {
        #pragma unroll 1
        for (int i = 0; i < 16; ++i) {
            const unsigned* p = basep + 2 * i;
            const unsigned pk0 = p[o0];
            const unsigned pk1 = p[o1];
            const unsigned pk2 = p[o2];
            const unsigned pk3 = has3 ? p[o3] : SENT2;

            // ---- 128-bin packed histogram (bin = key >> 8; SENT -> bin 123, harmless) ----
            *reinterpret_cast<uint4*>(&hst[lane * 4]) = make_uint4(0u, 0u, 0u, 0u);
            __syncwarp();
            atomicAdd(&hst[(pk0 >> 8) & 0xFFu], 1u);  atomicAdd(&hst[pk0 >> 24], 0x10000u);
            atomicAdd(&hst[(pk1 >> 8) & 0xFFu], 1u);  atomicAdd(&hst[pk1 >> 24], 0x10000u);
            atomicAdd(&hst[(pk2 >> 8) & 0xFFu], 1u);  atomicAdd(&hst[pk2 >> 24], 0x10000u);
            atomicAdd(&hst[(pk3 >> 8) & 0xFFu], 1u);  atomicAdd(&hst[pk3 >> 24], 0x10000u);
            __syncwarp();

            // ---- lane-serial prefix over own 4 bins + packed warp scan of totals ----
            const uint4 cw = *reinterpret_cast<const uint4*>(&hst[lane * 4]);
            unsigned q0 = cw.x;
            unsigned q1 = q0 + cw.y;
            unsigned q2 = q1 + cw.z;
            unsigned q3 = q2 + cw.w;
            unsigned incl = q3;
            #pragma unroll
            for (int d = 1; d < 32; d <<= 1) {
                unsigned t = __shfl_up_sync(0xffffffffu, incl, d);
                if (lane >= d) incl += t;
            }
            const unsigned excl = incl - q3;
            q0 += excl; q1 += excl; q2 += excl; q3 += excl;

            // ---- byte-SIMD bucket search: gather cum counts into bytes ----
            const unsigned xP = __byte_perm(q0, q1, 0x0040);
            const unsigned yP = __byte_perm(q2, q3, 0x0040);
            const unsigned bytesP = __byte_perm(xP, yP, 0x5410);   // (q0P,q1P,q2P,q3P)
            const unsigned xQ = __byte_perm(q0, q1, 0x0062);
            const unsigned yQ = __byte_perm(q2, q3, 0x0062);
            const unsigned bytesQ = __byte_perm(xQ, yQ, 0x5410);   // (q0Q,q1Q,q2Q,q3Q)

            // bins with cum <= 30 / 94 (borrow trick; bytes <= 128, no cross-borrow)
            const unsigned f30P = ((0x9E9E9E9Eu - bytesP) >> 7) & 0x01010101u;
            const unsigned f94P = ((0xDEDEDEDEu - bytesP) >> 7) & 0x01010101u;
            const unsigned f30Q = ((0x9E9E9E9Eu - bytesQ) >> 7) & 0x01010101u;
            const unsigned f94Q = ((0xDEDEDEDEu - bytesQ) >> 7) & 0x01010101u;

            unsigned w = (unsigned)__popc(f30P) | ((unsigned)__popc(f94P) << 8)
                       | ((unsigned)__popc(f30Q) << 16) | ((unsigned)__popc(f94Q) << 24);
            w = __reduce_add_sync(0xffffffffu, w);   // bytes: (bAP, bBP, bAQ, bBQ)

            // bucket base = bin<<8: place bytes at halfword-high positions
            const unsigned A2 = __byte_perm(w, 0, 0x2404);   // (0,bAP,0,bAQ)
            const unsigned B2 = __byte_perm(w, 0, 0x3414);   // (0,bBP,0,bBQ)

            float scP, scQ;
            bisect_pair<7, 7>(pk0, pk1, pk2, pk3, A2, B2, scP, scQ);
            if (lane == 2 * i)     myscale = scP;
            if (lane == 2 * i + 1) myscale = scQ;
        }
    } else {
        #pragma unroll 1
        for (int i = 0; i < 16; ++i) {
            const unsigned* p = basep + 2 * i;
            const unsigned pk0 = p[o0];
            const unsigned pk1 = p[o1];
            const unsigned pk2 = p[o2];
            const unsigned pk3 = has3 ? p[o3] : SENT2;

            float scP, scQ;
            bisect_pair<14, 0>(pk0, pk1, pk2, pk3, 0x04000400u, 0x04000400u, scP, scQ);
            if (lane == 2 * i)     myscale = scP;
            if (lane == 2 * i + 1) myscale = scQ;
        }
    }

    out[(size_t)bz * H * W + py * W + px0 + lane] = centerf * myscale;
}

extern "C" void kernel_launch(void* const* d_in, const int* in_sizes, int n_in,
                              void* d_out, int out_size)
{
    const float* in = (const float*)d_in[0];
    float* out = (float*)d_out;
    const int H = 512, W = 512;
    const int B = in_sizes[0] / (H * W);

    dim3 grid(W / 32, H / 8, B);
    dim3 block(256);
    tmcfar_kernel<<<grid, block>>>(in, out, H, W);
}

// round 7
// speedup vs baseline: 3.2336x; 1.0886x over previous
#include <cuda_runtime.h>
#include <cuda_fp16.h>
#include <cstdint>

// TM-CFAR: out = rd_map / trimmed_mean(sorted 126 reference cells, ranks [31,94))
// Window 9x15, guard 3x3, zero padding.
//
// Round-7: warp per 2 pixels.
//  - packed u32 key tile: entry c = (key[c] | key[c+1]<<16)
//  - interior: 128-bin packed histogram (bin = key>>8, P=hw0/Q=hw1) located via
//    uint4 ld + lane-serial prefix + one packed warp scan + byte-SIMD popc
//    bucket search (ONE REDUX) -> 256-wide bracket used DIRECTLY
//    (no bisection step; midpoint +-128 substitution in the closed form)
//  - border blocks: exact full bisection bits 14..0 (zero-padding ties)

#define TILE_WP   80      // packed tile stride in u32 (80 % 32 == 16: bank spread)
#define TILE_COLS 46
#define TILE_ROWS 16
#define KBIAS     1024
#define KSCALE    30720.0f
#define SENT2     0x7BFF7BFFu   // max-finite fp16: never below any threshold, hmul-safe

static __device__ __forceinline__ unsigned h2u(__half2 h) { return *reinterpret_cast<unsigned*>(&h); }
static __device__ __forceinline__ __half2  u2h(unsigned u) { return *reinterpret_cast<__half2*>(&u); }

// STARTBIT < STOPBIT => zero bisection steps, epilogue only, MIDOFF = 1<<(STOPBIT-1)
template <int STARTBIT, int STOPBIT>
static __device__ __forceinline__ void bisect_pair(
    unsigned pk0, unsigned pk1, unsigned pk2, unsigned pk3,
    unsigned A2, unsigned B2,
    float& scP, float& scQ)
{
    const __half2 magic = u2h(0x64006400u);   // (1024.0, 1024.0)

    #pragma unroll
    for (int bit = STARTBIT; bit >= STOPBIT; --bit) {
        const unsigned step2 = (1u << bit) * 0x10001u;
        const __half2 mA = u2h(A2 + step2);
        const __half2 mB = u2h(B2 + step2);

        __half2 sA = __hadd2(__hadd2(__hlt2(u2h(pk0), mA), __hlt2(u2h(pk1), mA)),
                             __hadd2(__hlt2(u2h(pk2), mA), __hlt2(u2h(pk3), mA)));
        __half2 sB = __hadd2(__hadd2(__hlt2(u2h(pk0), mB), __hlt2(u2h(pk1), mB)),
                             __hadd2(__hlt2(u2h(pk2), mB), __hlt2(u2h(pk3), mB)));
        const unsigned Ar = h2u(__hadd2(sA, magic));   // bytes (cAP, 0x64, cAQ, 0x64)
        const unsigned Br = h2u(__hadd2(sB, magic));
        unsigned cc = __byte_perm(Ar, Br, 0x6420);     // (cAP, cAQ, cBP, cBQ)
        cc = __reduce_add_sync(0xffffffffu, cc);

        // byte-wise accept flags: bytes 0,1 vs 30 ; bytes 2,3 vs 94
        const unsigned f = ((0xDEDE9E9Eu - cc) >> 7) & 0x01010101u;
        A2 += __byte_perm(f, 0, 0x4140) << bit;   // (fAP | fAQ<<16) << bit
        B2 += __byte_perm(f, 0, 0x4342) << bit;
    }

    const int MIDOFF = (STOPBIT > 0) ? (1 << (STOPBIT - 1)) : 0;

    // ---- epilogue: exact counts below brackets + masked range sums ----
    const __half2 hA = u2h(A2), hB = u2h(B2);
    const __half2 lA0 = __hlt2(u2h(pk0), hA), lA1 = __hlt2(u2h(pk1), hA);
    const __half2 lA2v = __hlt2(u2h(pk2), hA), lA3 = __hlt2(u2h(pk3), hA);
    const __half2 lB0 = __hlt2(u2h(pk0), hB), lB1 = __hlt2(u2h(pk1), hB);
    const __half2 lB2v = __hlt2(u2h(pk2), hB), lB3 = __hlt2(u2h(pk3), hB);

    const unsigned in0 = h2u(lB0) & ~h2u(lA0);
    const unsigned in1 = h2u(lB1) & ~h2u(lA1);
    const unsigned in2 = h2u(lB2v) & ~h2u(lA2v);
    const unsigned in3 = h2u(lB3) & ~h2u(lA3);

    const unsigned km0 = h2u(__hmul2(u2h(pk0), u2h(in0)));
    const unsigned km1 = h2u(__hmul2(u2h(pk1), u2h(in1)));
    const unsigned km2 = h2u(__hmul2(u2h(pk2), u2h(in2)));
    const unsigned km3 = h2u(__hmul2(u2h(pk3), u2h(in3)));

    // halfword-pair pack + SIMD add (lanes <= 2*31743, no carry)
    const unsigned lo01 = __byte_perm(km0, km1, 0x5410);
    const unsigned lo23 = __byte_perm(km2, km3, 0x5410);
    const unsigned hi01 = __byte_perm(km0, km1, 0x7632);
    const unsigned hi23 = __byte_perm(km2, km3, 0x7632);
    const unsigned vlo = __vadd2(lo01, lo23);
    const unsigned vhi = __vadd2(hi01, hi23);
    unsigned sP = (vlo & 0xFFFFu) + (vlo >> 16);
    unsigned sQ = (vhi & 0xFFFFu) + (vhi >> 16);

    const __half2 cA2 = __hadd2(__hadd2(lA0, lA1), __hadd2(lA2v, lA3));
    const __half2 cB2 = __hadd2(__hadd2(lB0, lB1), __hadd2(lB2v, lB3));
    unsigned ccf = __byte_perm(h2u(__hadd2(cA2, magic)), h2u(__hadd2(cB2, magic)), 0x6420);

    ccf = __reduce_add_sync(0xffffffffu, ccf);
    sP  = __reduce_add_sync(0xffffffffu, sP);
    sQ  = __reduce_add_sync(0xffffffffu, sQ);

    const int cAP = (int)(ccf & 255u);
    const int cAQ = (int)((ccf >> 8) & 255u);
    const int cBP = (int)((ccf >> 16) & 255u);
    const int cBQ = (int)(ccf >> 24);

    const int TAP = (int)(A2 & 0xFFFFu) + MIDOFF, TAQ = (int)(A2 >> 16) + MIDOFF;
    const int TBP = (int)(B2 & 0xFFFFu) + MIDOFF, TBQ = (int)(B2 >> 16) + MIDOFF;

    const int keptP = (int)sP - KBIAS * (cBP - cAP)
                    + (94 - cBP) * (TBP - KBIAS) - (31 - cAP) * (TAP - KBIAS);
    const int keptQ = (int)sQ - KBIAS * (cBQ - cAQ)
                    + (94 - cBQ) * (TBQ - KBIAS) - (31 - cAQ) * (TAQ - KBIAS);

    scP = __fdividef(63.0f * KSCALE, (float)keptP);
    scQ = __fdividef(63.0f * KSCALE, (float)keptQ);
}

__global__ __launch_bounds__(256, 7)
void tmcfar_kernel(const float* __restrict__ in, float* __restrict__ out,
                   int H, int W)
{
    __shared__ unsigned keypack[TILE_ROWS * TILE_WP];        // 5120 B
    __shared__ int      offs[128];                           // u32-element offsets
    __shared__ __align__(16) unsigned hist[8][128];          // 128 bins, P=hw0 Q=hw1

    const int tid  = threadIdx.x;
    const int lane = tid & 31;
    const int wrp  = tid >> 5;
    const int bz   = blockIdx.z;
    const int py0  = blockIdx.y * 8;
    const int px0  = blockIdx.x * 32;

    // compacted (dy,dx) offsets of the 126 reference cells (u32-element units)
    if (tid < 135) {
        int r = tid / 15, c = tid - r * 15;
        bool guard = (r >= 3 && r <= 5 && c >= 6 && c <= 8);
        if (!guard) {
            int rowsBefore = min(max(r - 3, 0), 3);
            int sameRow    = (r >= 3 && r <= 5) ? min(max(c - 6, 0), 3) : 0;
            int gb = 3 * rowsBefore + sameRow;
            offs[tid - gb] = (r - 4) * TILE_WP + (c - 7);
        }
    }

    // load + quantize directly into packed tile: entry c = key[c] | key[c+1]<<16
    const int gy0 = py0 - 4, gx0 = px0 - 7;
    const float* inb = in + (size_t)bz * H * W;
    for (int idx = tid; idx < TILE_ROWS * 64; idx += 256) {
        int r = idx >> 6, c = idx & 63;
        if (c < TILE_COLS - 1) {
            int gy = gy0 + r, gx = gx0 + c;
            bool okr = (gy >= 0 && gy < H);
            float v0 = (okr && gx >= 0     && gx < W)     ? inb[gy * W + gx]     : 0.0f;
            float v1 = (okr && gx + 1 >= 0 && gx + 1 < W) ? inb[gy * W + gx + 1] : 0.0f;
            unsigned k0 = min((unsigned)(v0 * KSCALE), 30719u) + (unsigned)KBIAS;
            unsigned k1 = min((unsigned)(v1 * KSCALE), 30719u) + (unsigned)KBIAS;
            keypack[r * TILE_WP + c] = k0 | (k1 << 16);
        }
    }
    __syncthreads();

    const bool border = (blockIdx.x == 0) | (blockIdx.x == gridDim.x - 1) |
                        (blockIdx.y == 0) | (blockIdx.y == gridDim.y - 1);

    const int py = py0 + wrp;
    const float centerf = inb[py * W + px0 + lane];

    const int o0 = offs[lane];
    const int o1 = offs[lane + 32];
    const int o2 = offs[lane + 64];
    const int o3 = (lane < 30) ? offs[lane + 96] : 0;
    const bool has3 = (lane < 30);

    const unsigned* basep = &keypack[(wrp + 4) * TILE_WP + 7];
    unsigned* hst = &hist[wrp][0];
    float myscale = 0.0f;

    if (!border) {
        #pragma unroll 1
        for (int i = 0; i < 16; ++i) {
            const unsigned* p = basep + 2 * i;
            const unsigned pk0 = p[o0];
            const unsigned pk1 = p[o1];
            const unsigned pk2 = p[o2];
            const unsigned pk3 = has3 ? p[o3] : SENT2;

            // ---- 128-bin packed histogram (bin = key >> 8; SENT -> bin 123, harmless) ----
            *reinterpret_cast<uint4*>(&hst[lane * 4]) = make_uint4(0u, 0u, 0u, 0u);
            __syncwarp();
            atomicAdd(&hst[(pk0 >> 8) & 0xFFu], 1u);  atomicAdd(&hst[pk0 >> 24], 0x10000u);
            atomicAdd(&hst[(pk1 >> 8) & 0xFFu], 1u);  atomicAdd(&hst[pk1 >> 24], 0x10000u);
            atomicAdd(&hst[(pk2 >> 8) & 0xFFu], 1u);  atomicAdd(&hst[pk2 >> 24], 0x10000u);
            atomicAdd(&hst[(pk3 >> 8) & 0xFFu], 1u);  atomicAdd(&hst[pk3 >> 24], 0x10000u);
            __syncwarp();

            // ---- lane-serial prefix over own 4 bins + packed warp scan of totals ----
            const uint4 cw = *reinterpret_cast<const uint4*>(&hst[lane * 4]);
            unsigned q0 = cw.x;
            unsigned q1 = q0 + cw.y;
            unsigned q2 = q1 + cw.z;
            unsigned q3 = q2 + cw.w;
            unsigned incl = q3;
            #pragma unroll
            for (int d = 1; d < 32; d <<= 1) {
                unsigned t = __shfl_up_sync(0xffffffffu, incl, d);
                if (lane >= d) incl += t;
            }
            const unsigned excl = incl - q3;
            q0 += excl; q1 += excl; q2 += excl; q3 += excl;

            // ---- byte-SIMD bucket search: gather cum counts into bytes ----
            const unsigned xP = __byte_perm(q0, q1, 0x0040);
            const unsigned yP = __byte_perm(q2, q3, 0x0040);
            const unsigned bytesP = __byte_perm(xP, yP, 0x5410);   // (q0P,q1P,q2P,q3P)
            const unsigned xQ = __byte_perm(q0, q1, 0x0062);
            const unsigned yQ = __byte_perm(q2, q3, 0x0062);
            const unsigned bytesQ = __byte_perm(xQ, yQ, 0x5410);   // (q0Q,q1Q,q2Q,q3Q)

            // bins with cum <= 30 / 94 (borrow trick; bytes <= 128, no cross-borrow)
            const unsigned f30P = ((0x9E9E9E9Eu - bytesP) >> 7) & 0x01010101u;
            const unsigned f94P = ((0xDEDEDEDEu - bytesP) >> 7) & 0x01010101u;
            const unsigned f30Q = ((0x9E9E9E9Eu - bytesQ) >> 7) & 0x01010101u;
            const unsigned f94Q = ((0xDEDEDEDEu - bytesQ) >> 7) & 0x01010101u;

            unsigned w = (unsigned)__popc(f30P) | ((unsigned)__popc(f94P) << 8)
                       | ((unsigned)__popc(f30Q) << 16) | ((unsigned)__popc(f94Q) << 24);
            w = __reduce_add_sync(0xffffffffu, w);   // bytes: (bAP, bBP, bAQ, bBQ)

            // bucket base = bin<<8: place bytes at halfword-high positions
            const unsigned A2 = __byte_perm(w, 0, 0x2404);   // (0,bAP,0,bAQ)
            const unsigned B2 = __byte_perm(w, 0, 0x3414);   // (0,bBP,0,bBQ)

            float scP, scQ;
            // zero bisection steps: bracket = full 256-wide bucket, MIDOFF = 128
            bisect_pair<7, 8>(pk0, pk1, pk2, pk3, A2, B2, scP, scQ);
            if (lane == 2 * i)     myscale = scP;
            if (lane == 2 * i + 1) myscale = scQ;
        }
    } else {
        #pragma unroll 1
        for (int i = 0; i < 16; ++i) {
            const unsigned* p = basep + 2 * i;
            const unsigned pk0 = p[o0];
            const unsigned pk1 = p[o1];
            const unsigned pk2 = p[o2];
            const unsigned pk3 = has3 ? p[o3] : SENT2;

            float scP, scQ;
            bisect_pair<14, 0>(pk0, pk1, pk2, pk3, 0x04000400u, 0x04000400u, scP, scQ);
            if (lane == 2 * i)     myscale = scP;
            if (lane == 2 * i + 1) myscale = scQ;
        }
    }

    out[(size_t)bz * H * W + py * W + px0 + lane] = centerf * myscale;
}

extern "C" void kernel_launch(void* const* d_in, const int* in_sizes, int n_in,
                              void* d_out, int out_size)
{
    const float* in = (const float*)d_in[0];
    float* out = (float*)d_out;
    const int H = 512, W = 512;
    const int B = in_sizes[0] / (H * W);

    dim3 grid(W / 32, H / 8, B);
    dim3 block(256);
    tmcfar_kernel<<<grid, block>>>(in, out, H, W);
}

// round 8
// speedup vs baseline: 3.4203x; 1.0577x over previous
#include <cuda_runtime.h>
#include <cuda_fp16.h>
#include <cstdint>

// TM-CFAR: out = rd_map / trimmed_mean(sorted 126 reference cells, ranks [31,94))
// Window 9x15, guard 3x3, zero padding.
//
// Round-8: warp per 2 pixels, unified path.
//  - packed u32 key tile: entry c = (key[c] | key[c+1]<<16)
//  - EVERY pair: 128-bin packed histogram (bin = key>>8, P=hw0/Q=hw1),
//    uint4 ld + lane-serial prefix + packed warp scan + byte-SIMD popc bucket
//    search (ONE REDUX) -> exact 256-wide bracket containing ranks 30 / 94
//  - clean pairs (window fully inside image): bracket used directly,
//    midpoint +-128 substitution (zero bisection steps)
//  - padding-affected pairs (px<7 | px>=W-7 | py<4 | py>=H-4): 8 exact
//    bisection steps inside the bracket + exact tie-aware epilogue

#define TILE_WP   80      // packed tile stride in u32 (80 % 32 == 16: bank spread)
#define TILE_COLS 46
#define TILE_ROWS 16
#define KBIAS     1024
#define KSCALE    30720.0f
#define SENT2     0x7BFF7BFFu   // max-finite fp16: never below any threshold, hmul-safe

static __device__ __forceinline__ unsigned h2u(__half2 h) { return *reinterpret_cast<unsigned*>(&h); }
static __device__ __forceinline__ __half2  u2h(unsigned u) { return *reinterpret_cast<__half2*>(&u); }

// STARTBIT < STOPBIT => zero bisection steps, epilogue only, MIDOFF = 1<<(STOPBIT-1)
template <int STARTBIT, int STOPBIT>
static __device__ __forceinline__ void bisect_pair(
    unsigned pk0, unsigned pk1, unsigned pk2, unsigned pk3,
    unsigned A2, unsigned B2,
    float& scP, float& scQ)
{
    const __half2 magic = u2h(0x64006400u);   // (1024.0, 1024.0)

    #pragma unroll
    for (int bit = STARTBIT; bit >= STOPBIT; --bit) {
        const unsigned step2 = (1u << bit) * 0x10001u;
        const __half2 mA = u2h(A2 + step2);
        const __half2 mB = u2h(B2 + step2);

        __half2 sA = __hadd2(__hadd2(__hlt2(u2h(pk0), mA), __hlt2(u2h(pk1), mA)),
                             __hadd2(__hlt2(u2h(pk2), mA), __hlt2(u2h(pk3), mA)));
        __half2 sB = __hadd2(__hadd2(__hlt2(u2h(pk0), mB), __hlt2(u2h(pk1), mB)),
                             __hadd2(__hlt2(u2h(pk2), mB), __hlt2(u2h(pk3), mB)));
        const unsigned Ar = h2u(__hadd2(sA, magic));   // bytes (cAP, 0x64, cAQ, 0x64)
        const unsigned Br = h2u(__hadd2(sB, magic));
        unsigned cc = __byte_perm(Ar, Br, 0x6420);     // (cAP, cAQ, cBP, cBQ)
        cc = __reduce_add_sync(0xffffffffu, cc);

        // byte-wise accept flags: bytes 0,1 vs 30 ; bytes 2,3 vs 94
        const unsigned f = ((0xDEDE9E9Eu - cc) >> 7) & 0x01010101u;
        A2 += __byte_perm(f, 0, 0x4140) << bit;   // (fAP | fAQ<<16) << bit
        B2 += __byte_perm(f, 0, 0x4342) << bit;
    }

    const int MIDOFF = (STOPBIT > 0) ? (1 << (STOPBIT - 1)) : 0;

    // ---- epilogue: exact counts below brackets + masked range sums ----
    const __half2 hA = u2h(A2), hB = u2h(B2);
    const __half2 lA0 = __hlt2(u2h(pk0), hA), lA1 = __hlt2(u2h(pk1), hA);
    const __half2 lA2v = __hlt2(u2h(pk2), hA), lA3 = __hlt2(u2h(pk3), hA);
    const __half2 lB0 = __hlt2(u2h(pk0), hB), lB1 = __hlt2(u2h(pk1), hB);
    const __half2 lB2v = __hlt2(u2h(pk2), hB), lB3 = __hlt2(u2h(pk3), hB);

    const unsigned in0 = h2u(lB0) & ~h2u(lA0);
    const unsigned in1 = h2u(lB1) & ~h2u(lA1);
    const unsigned in2 = h2u(lB2v) & ~h2u(lA2v);
    const unsigned in3 = h2u(lB3) & ~h2u(lA3);

    const unsigned km0 = h2u(__hmul2(u2h(pk0), u2h(in0)));
    const unsigned km1 = h2u(__hmul2(u2h(pk1), u2h(in1)));
    const unsigned km2 = h2u(__hmul2(u2h(pk2), u2h(in2)));
    const unsigned km3 = h2u(__hmul2(u2h(pk3), u2h(in3)));

    // halfword-pair pack + SIMD add (lanes <= 2*31743, no carry)
    const unsigned lo01 = __byte_perm(km0, km1, 0x5410);
    const unsigned lo23 = __byte_perm(km2, km3, 0x5410);
    const unsigned hi01 = __byte_perm(km0, km1, 0x7632);
    const unsigned hi23 = __byte_perm(km2, km3, 0x7632);
    const unsigned vlo = __vadd2(lo01, lo23);
    const unsigned vhi = __vadd2(hi01, hi23);
    unsigned sP = (vlo & 0xFFFFu) + (vlo >> 16);
    unsigned sQ = (vhi & 0xFFFFu) + (vhi >> 16);

    const __half2 cA2 = __hadd2(__hadd2(lA0, lA1), __hadd2(lA2v, lA3));
    const __half2 cB2 = __hadd2(__hadd2(lB0, lB1), __hadd2(lB2v, lB3));
    unsigned ccf = __byte_perm(h2u(__hadd2(cA2, magic)), h2u(__hadd2(cB2, magic)), 0x6420);

    ccf = __reduce_add_sync(0xffffffffu, ccf);
    sP  = __reduce_add_sync(0xffffffffu, sP);
    sQ  = __reduce_add_sync(0xffffffffu, sQ);

    const int cAP = (int)(ccf & 255u);
    const int cAQ = (int)((ccf >> 8) & 255u);
    const int cBP = (int)((ccf >> 16) & 255u);
    const int cBQ = (int)(ccf >> 24);

    const int TAP = (int)(A2 & 0xFFFFu) + MIDOFF, TAQ = (int)(A2 >> 16) + MIDOFF;
    const int TBP = (int)(B2 & 0xFFFFu) + MIDOFF, TBQ = (int)(B2 >> 16) + MIDOFF;

    const int keptP = (int)sP - KBIAS * (cBP - cAP)
                    + (94 - cBP) * (TBP - KBIAS) - (31 - cAP) * (TAP - KBIAS);
    const int keptQ = (int)sQ - KBIAS * (cBQ - cAQ)
                    + (94 - cBQ) * (TBQ - KBIAS) - (31 - cAQ) * (TAQ - KBIAS);

    scP = __fdividef(63.0f * KSCALE, (float)keptP);
    scQ = __fdividef(63.0f * KSCALE, (float)keptQ);
}

__global__ __launch_bounds__(256, 7)
void tmcfar_kernel(const float* __restrict__ in, float* __restrict__ out,
                   int H, int W)
{
    __shared__ unsigned keypack[TILE_ROWS * TILE_WP];        // 5120 B
    __shared__ int      offs[128];                           // u32-element offsets
    __shared__ __align__(16) unsigned hist[8][128];          // 128 bins, P=hw0 Q=hw1

    const int tid  = threadIdx.x;
    const int lane = tid & 31;
    const int wrp  = tid >> 5;
    const int bz   = blockIdx.z;
    const int py0  = blockIdx.y * 8;
    const int px0  = blockIdx.x * 32;

    // compacted (dy,dx) offsets of the 126 reference cells (u32-element units)
    if (tid < 135) {
        int r = tid / 15, c = tid - r * 15;
        bool guard = (r >= 3 && r <= 5 && c >= 6 && c <= 8);
        if (!guard) {
            int rowsBefore = min(max(r - 3, 0), 3);
            int sameRow    = (r >= 3 && r <= 5) ? min(max(c - 6, 0), 3) : 0;
            int gb = 3 * rowsBefore + sameRow;
            offs[tid - gb] = (r - 4) * TILE_WP + (c - 7);
        }
    }

    // load + quantize directly into packed tile: entry c = key[c] | key[c+1]<<16
    const int gy0 = py0 - 4, gx0 = px0 - 7;
    const float* inb = in + (size_t)bz * H * W;
    for (int idx = tid; idx < TILE_ROWS * 64; idx += 256) {
        int r = idx >> 6, c = idx & 63;
        if (c < TILE_COLS - 1) {
            int gy = gy0 + r, gx = gx0 + c;
            bool okr = (gy >= 0 && gy < H);
            float v0 = (okr && gx >= 0     && gx < W)     ? inb[gy * W + gx]     : 0.0f;
            float v1 = (okr && gx + 1 >= 0 && gx + 1 < W) ? inb[gy * W + gx + 1] : 0.0f;
            unsigned k0 = min((unsigned)(v0 * KSCALE), 30719u) + (unsigned)KBIAS;
            unsigned k1 = min((unsigned)(v1 * KSCALE), 30719u) + (unsigned)KBIAS;
            keypack[r * TILE_WP + c] = k0 | (k1 << 16);
        }
    }
    __syncthreads();

    const int py = py0 + wrp;
    const float centerf = inb[py * W + px0 + lane];
    const bool exY = (py < 4) | (py >= H - 4);   // warp-uniform

    const int o0 = offs[lane];
    const int o1 = offs[lane + 32];
    const int o2 = offs[lane + 64];
    const int o3 = (lane < 30) ? offs[lane + 96] : 0;
    const bool has3 = (lane < 30);

    const unsigned* basep = &keypack[(wrp + 4) * TILE_WP + 7];
    unsigned* hst = &hist[wrp][0];
    float myscale = 0.0f;

    #pragma unroll 1
    for (int i = 0; i < 16; ++i) {
        const unsigned* p = basep + 2 * i;
        const unsigned pk0 = p[o0];
        const unsigned pk1 = p[o1];
        const unsigned pk2 = p[o2];
        const unsigned pk3 = has3 ? p[o3] : SENT2;

        // ---- 128-bin packed histogram (bin = key >> 8; SENT -> bin 123, harmless) ----
        *reinterpret_cast<uint4*>(&hst[lane * 4]) = make_uint4(0u, 0u, 0u, 0u);
        __syncwarp();
        atomicAdd(&hst[(pk0 >> 8) & 0xFFu], 1u);  atomicAdd(&hst[pk0 >> 24], 0x10000u);
        atomicAdd(&hst[(pk1 >> 8) & 0xFFu], 1u);  atomicAdd(&hst[pk1 >> 24], 0x10000u);
        atomicAdd(&hst[(pk2 >> 8) & 0xFFu], 1u);  atomicAdd(&hst[pk2 >> 24], 0x10000u);
        atomicAdd(&hst[(pk3 >> 8) & 0xFFu], 1u);  atomicAdd(&hst[pk3 >> 24], 0x10000u);
        __syncwarp();

        // ---- lane-serial prefix over own 4 bins + packed warp scan of totals ----
        const uint4 cw = *reinterpret_cast<const uint4*>(&hst[lane * 4]);
        unsigned q0 = cw.x;
        unsigned q1 = q0 + cw.y;
        unsigned q2 = q1 + cw.z;
        unsigned q3 = q2 + cw.w;
        unsigned incl = q3;
        #pragma unroll
        for (int d = 1; d < 32; d <<= 1) {
            unsigned t = __shfl_up_sync(0xffffffffu, incl, d);
            if (lane >= d) incl += t;
        }
        const unsigned excl = incl - q3;
        q0 += excl; q1 += excl; q2 += excl; q3 += excl;

        // ---- byte-SIMD bucket search: gather cum counts into bytes ----
        const unsigned xP = __byte_perm(q0, q1, 0x0040);
        const unsigned yP = __byte_perm(q2, q3, 0x0040);
        const unsigned bytesP = __byte_perm(xP, yP, 0x5410);   // (q0P,q1P,q2P,q3P)
        const unsigned xQ = __byte_perm(q0, q1, 0x0062);
        const unsigned yQ = __byte_perm(q2, q3, 0x0062);
        const unsigned bytesQ = __byte_perm(xQ, yQ, 0x5410);   // (q0Q,q1Q,q2Q,q3Q)

        // bins with cum <= 30 / 94 (borrow trick; bytes <= 128, no cross-borrow)
        const unsigned f30P = ((0x9E9E9E9Eu - bytesP) >> 7) & 0x01010101u;
        const unsigned f94P = ((0xDEDEDEDEu - bytesP) >> 7) & 0x01010101u;
        const unsigned f30Q = ((0x9E9E9E9Eu - bytesQ) >> 7) & 0x01010101u;
        const unsigned f94Q = ((0xDEDEDEDEu - bytesQ) >> 7) & 0x01010101u;

        unsigned w = (unsigned)__popc(f30P) | ((unsigned)__popc(f94P) << 8)
                   | ((unsigned)__popc(f30Q) << 16) | ((unsigned)__popc(f94Q) << 24);
        w = __reduce_add_sync(0xffffffffu, w);   // bytes: (bAP, bBP, bAQ, bBQ)

        // bucket base = bin<<8: place bytes at halfword-high positions
        const unsigned A2 = __byte_perm(w, 0, 0x2404);   // (0,bAP,0,bAQ)
        const unsigned B2 = __byte_perm(w, 0, 0x3414);   // (0,bBP,0,bBQ)

        float scP, scQ;
        const int pxP = px0 + 2 * i;
        if (exY | (pxP < 7) | (pxP + 1 >= W - 7)) {
            // window touches zero padding: 8 exact bisection steps inside bucket
            bisect_pair<7, 0>(pk0, pk1, pk2, pk3, A2, B2, scP, scQ);
        } else {
            // clean: 256-wide bucket direct, midpoint +-128 substitution
            bisect_pair<7, 8>(pk0, pk1, pk2, pk3, A2, B2, scP, scQ);
        }
        if (lane == 2 * i)     myscale = scP;
        if (lane == 2 * i + 1) myscale = scQ;
    }

    out[(size_t)bz * H * W + py * W + px0 + lane] = centerf * myscale;
}

extern "C" void kernel_launch(void* const* d_in, const int* in_sizes, int n_in,
                              void* d_out, int out_size)
{
    const float* in = (const float*)d_in[0];
    float* out = (float*)d_out;
    const int H = 512, W = 512;
    const int B = in_sizes[0] / (H * W);

    dim3 grid(W / 32, H / 8, B);
    dim3 block(256);
    tmcfar_kernel<<<grid, block>>>(in, out, H, W);
}

// round 9
// speedup vs baseline: 3.9315x; 1.1494x over previous
#include <cuda_runtime.h>
#include <cuda_fp16.h>
#include <cstdint>

// TM-CFAR: out = rd_map / trimmed_mean(sorted 126 reference cells, ranks [31,94))
// Window 9x15, guard 3x3, zero padding.
//
// Round-9: warp per 4 pixels (P,Q,R,S), byte-packed histogram.
//  - packed u32 key tile: entry c = (key[c] | key[c+1]<<16)
//  - 128-bin histogram, ONE u32/bin, byte p = count for pixel p (counts<=128)
//  - ONE clear + ONE uint4 cum load + ONE warp scan + borrow-trick byte flags
//    + TWO REDUX locate the 256-wide rank-30/94 buckets for ALL 4 pixels
//  - clean quads: bucket direct, midpoint +-128 substitution (epilogue only)
//  - padding-affected quads: 8 exact bisection steps inside bucket, per pair

#define TILE_WP   80      // packed tile stride in u32 (80 % 32 == 16: bank spread)
#define TILE_COLS 46
#define TILE_ROWS 16
#define KBIAS     1024
#define KSCALE    30720.0f
#define SENT2     0x7BFF7BFFu   // max-finite fp16: never below any threshold, hmul-safe

static __device__ __forceinline__ unsigned h2u(__half2 h) { return *reinterpret_cast<unsigned*>(&h); }
static __device__ __forceinline__ __half2  u2h(unsigned u) { return *reinterpret_cast<__half2*>(&u); }

// STARTBIT < STOPBIT => zero bisection steps, epilogue only, MIDOFF = 1<<(STOPBIT-1)
template <int STARTBIT, int STOPBIT>
static __device__ __forceinline__ void bisect_pair(
    unsigned pk0, unsigned pk1, unsigned pk2, unsigned pk3,
    unsigned A2, unsigned B2,
    float& scP, float& scQ)
{
    const __half2 magic = u2h(0x64006400u);   // (1024.0, 1024.0)

    #pragma unroll
    for (int bit = STARTBIT; bit >= STOPBIT; --bit) {
        const unsigned step2 = (1u << bit) * 0x10001u;
        const __half2 mA = u2h(A2 + step2);
        const __half2 mB = u2h(B2 + step2);

        __half2 sA = __hadd2(__hadd2(__hlt2(u2h(pk0), mA), __hlt2(u2h(pk1), mA)),
                             __hadd2(__hlt2(u2h(pk2), mA), __hlt2(u2h(pk3), mA)));
        __half2 sB = __hadd2(__hadd2(__hlt2(u2h(pk0), mB), __hlt2(u2h(pk1), mB)),
                             __hadd2(__hlt2(u2h(pk2), mB), __hlt2(u2h(pk3), mB)));
        const unsigned Ar = h2u(__hadd2(sA, magic));   // bytes (cAP, 0x64, cAQ, 0x64)
        const unsigned Br = h2u(__hadd2(sB, magic));
        unsigned cc = __byte_perm(Ar, Br, 0x6420);     // (cAP, cAQ, cBP, cBQ)
        cc = __reduce_add_sync(0xffffffffu, cc);

        // byte-wise accept flags: bytes 0,1 vs 30 ; bytes 2,3 vs 94
        const unsigned f = ((0xDEDE9E9Eu - cc) >> 7) & 0x01010101u;
        A2 += __byte_perm(f, 0, 0x4140) << bit;   // (fAP | fAQ<<16) << bit
        B2 += __byte_perm(f, 0, 0x4342) << bit;
    }

    const int MIDOFF = (STOPBIT > 0) ? (1 << (STOPBIT - 1)) : 0;

    // ---- epilogue: exact counts below brackets + masked range sums ----
    const __half2 hA = u2h(A2), hB = u2h(B2);
    const __half2 lA0 = __hlt2(u2h(pk0), hA), lA1 = __hlt2(u2h(pk1), hA);
    const __half2 lA2v = __hlt2(u2h(pk2), hA), lA3 = __hlt2(u2h(pk3), hA);
    const __half2 lB0 = __hlt2(u2h(pk0), hB), lB1 = __hlt2(u2h(pk1), hB);
    const __half2 lB2v = __hlt2(u2h(pk2), hB), lB3 = __hlt2(u2h(pk3), hB);

    const unsigned in0 = h2u(lB0) & ~h2u(lA0);
    const unsigned in1 = h2u(lB1) & ~h2u(lA1);
    const unsigned in2 = h2u(lB2v) & ~h2u(lA2v);
    const unsigned in3 = h2u(lB3) & ~h2u(lA3);

    const unsigned km0 = h2u(__hmul2(u2h(pk0), u2h(in0)));
    const unsigned km1 = h2u(__hmul2(u2h(pk1), u2h(in1)));
    const unsigned km2 = h2u(__hmul2(u2h(pk2), u2h(in2)));
    const unsigned km3 = h2u(__hmul2(u2h(pk3), u2h(in3)));

    // halfword-pair pack + SIMD add (lanes <= 2*31743, no carry)
    const unsigned lo01 = __byte_perm(km0, km1, 0x5410);
    const unsigned lo23 = __byte_perm(km2, km3, 0x5410);
    const unsigned hi01 = __byte_perm(km0, km1, 0x7632);
    const unsigned hi23 = __byte_perm(km2, km3, 0x7632);
    const unsigned vlo = __vadd2(lo01, lo23);
    const unsigned vhi = __vadd2(hi01, hi23);
    unsigned sP = (vlo & 0xFFFFu) + (vlo >> 16);
    unsigned sQ = (vhi & 0xFFFFu) + (vhi >> 16);

    const __half2 cA2 = __hadd2(__hadd2(lA0, lA1), __hadd2(lA2v, lA3));
    const __half2 cB2 = __hadd2(__hadd2(lB0, lB1), __hadd2(lB2v, lB3));
    unsigned ccf = __byte_perm(h2u(__hadd2(cA2, magic)), h2u(__hadd2(cB2, magic)), 0x6420);

    ccf = __reduce_add_sync(0xffffffffu, ccf);
    sP  = __reduce_add_sync(0xffffffffu, sP);
    sQ  = __reduce_add_sync(0xffffffffu, sQ);

    const int cAP = (int)(ccf & 255u);
    const int cAQ = (int)((ccf >> 8) & 255u);
    const int cBP = (int)((ccf >> 16) & 255u);
    const int cBQ = (int)(ccf >> 24);

    const int TAP = (int)(A2 & 0xFFFFu) + MIDOFF, TAQ = (int)(A2 >> 16) + MIDOFF;
    const int TBP = (int)(B2 & 0xFFFFu) + MIDOFF, TBQ = (int)(B2 >> 16) + MIDOFF;

    const int keptP = (int)sP - KBIAS * (cBP - cAP)
                    + (94 - cBP) * (TBP - KBIAS) - (31 - cAP) * (TAP - KBIAS);
    const int keptQ = (int)sQ - KBIAS * (cBQ - cAQ)
                    + (94 - cBQ) * (TBQ - KBIAS) - (31 - cAQ) * (TAQ - KBIAS);

    scP = __fdividef(63.0f * KSCALE, (float)keptP);
    scQ = __fdividef(63.0f * KSCALE, (float)keptQ);
}

__global__ __launch_bounds__(256, 6)
void tmcfar_kernel(const float* __restrict__ in, float* __restrict__ out,
                   int H, int W)
{
    __shared__ unsigned keypack[TILE_ROWS * TILE_WP];        // 5120 B
    __shared__ int      offs[128];                           // u32-element offsets
    __shared__ __align__(16) unsigned hist[8][128];          // byte p = pixel p count

    const int tid  = threadIdx.x;
    const int lane = tid & 31;
    const int wrp  = tid >> 5;
    const int bz   = blockIdx.z;
    const int py0  = blockIdx.y * 8;
    const int px0  = blockIdx.x * 32;

    // compacted (dy,dx) offsets of the 126 reference cells (u32-element units)
    if (tid < 135) {
        int r = tid / 15, c = tid - r * 15;
        bool guard = (r >= 3 && r <= 5 && c >= 6 && c <= 8);
        if (!guard) {
            int rowsBefore = min(max(r - 3, 0), 3);
            int sameRow    = (r >= 3 && r <= 5) ? min(max(c - 6, 0), 3) : 0;
            int gb = 3 * rowsBefore + sameRow;
            offs[tid - gb] = (r - 4) * TILE_WP + (c - 7);
        }
    }

    // load + quantize directly into packed tile: entry c = key[c] | key[c+1]<<16
    const int gy0 = py0 - 4, gx0 = px0 - 7;
    const float* inb = in + (size_t)bz * H * W;
    for (int idx = tid; idx < TILE_ROWS * 64; idx += 256) {
        int r = idx >> 6, c = idx & 63;
        if (c < TILE_COLS - 1) {
            int gy = gy0 + r, gx = gx0 + c;
            bool okr = (gy >= 0 && gy < H);
            float v0 = (okr && gx >= 0     && gx < W)     ? inb[gy * W + gx]     : 0.0f;
            float v1 = (okr && gx + 1 >= 0 && gx + 1 < W) ? inb[gy * W + gx + 1] : 0.0f;
            unsigned k0 = min((unsigned)(v0 * KSCALE), 30719u) + (unsigned)KBIAS;
            unsigned k1 = min((unsigned)(v1 * KSCALE), 30719u) + (unsigned)KBIAS;
            keypack[r * TILE_WP + c] = k0 | (k1 << 16);
        }
    }
    __syncthreads();

    const int py = py0 + wrp;
    const float centerf = inb[py * W + px0 + lane];
    const bool exY = (py < 4) | (py >= H - 4);   // warp-uniform

    const int o0 = offs[lane];
    const int o1 = offs[lane + 32];
    const int o2 = offs[lane + 64];
    const int o3 = (lane < 30) ? offs[lane + 96] : 0;
    const bool has3 = (lane < 30);

    const unsigned* basep = &keypack[(wrp + 4) * TILE_WP + 7];
    unsigned* hst = &hist[wrp][0];
    float myscale = 0.0f;

    #pragma unroll 1
    for (int i = 0; i < 8; ++i) {
        const unsigned* p = basep + 4 * i;
        // pair (P,Q) words and pair (R,S) words (R = P+2)
        const unsigned a0 = p[o0],     b0 = p[o0 + 2];
        const unsigned a1 = p[o1],     b1 = p[o1 + 2];
        const unsigned a2 = p[o2],     b2 = p[o2 + 2];
        const unsigned a3 = has3 ? p[o3]     : SENT2;
        const unsigned b3 = has3 ? p[o3 + 2] : SENT2;

        // ---- byte-packed 128-bin histogram (bin = key>>8; SENT->bin 123, harmless) ----
        *reinterpret_cast<uint4*>(&hst[lane * 4]) = make_uint4(0u, 0u, 0u, 0u);
        __syncwarp();
        atomicAdd(&hst[(a0 >> 8) & 0xFFu], 1u);         atomicAdd(&hst[a0 >> 24], 0x100u);
        atomicAdd(&hst[(a1 >> 8) & 0xFFu], 1u);         atomicAdd(&hst[a1 >> 24], 0x100u);
        atomicAdd(&hst[(a2 >> 8) & 0xFFu], 1u);         atomicAdd(&hst[a2 >> 24], 0x100u);
        atomicAdd(&hst[(a3 >> 8) & 0xFFu], 1u);         atomicAdd(&hst[a3 >> 24], 0x100u);
        atomicAdd(&hst[(b0 >> 8) & 0xFFu], 0x10000u);   atomicAdd(&hst[b0 >> 24], 0x1000000u);
        atomicAdd(&hst[(b1 >> 8) & 0xFFu], 0x10000u);   atomicAdd(&hst[b1 >> 24], 0x1000000u);
        atomicAdd(&hst[(b2 >> 8) & 0xFFu], 0x10000u);   atomicAdd(&hst[b2 >> 24], 0x1000000u);
        atomicAdd(&hst[(b3 >> 8) & 0xFFu], 0x10000u);   atomicAdd(&hst[b3 >> 24], 0x1000000u);
        __syncwarp();

        // ---- lane-serial byte-SIMD prefix + ONE packed warp scan (bytes <= 128) ----
        const uint4 cw = *reinterpret_cast<const uint4*>(&hst[lane * 4]);
        unsigned q0 = cw.x;
        unsigned q1 = q0 + cw.y;
        unsigned q2 = q1 + cw.z;
        unsigned q3 = q2 + cw.w;
        unsigned incl = q3;
        #pragma unroll
        for (int d = 1; d < 32; d <<= 1) {
            unsigned t = __shfl_up_sync(0xffffffffu, incl, d);
            if (lane >= d) incl += t;
        }
        const unsigned excl = incl - q3;
        q0 += excl; q1 += excl; q2 += excl; q3 += excl;

        // ---- byte-SIMD bucket search for all 4 pixels, TWO REDUX total ----
        const unsigned g30 = (((0x9E9E9E9Eu - q0) >> 7) & 0x01010101u)
                           + (((0x9E9E9E9Eu - q1) >> 7) & 0x01010101u)
                           + (((0x9E9E9E9Eu - q2) >> 7) & 0x01010101u)
                           + (((0x9E9E9E9Eu - q3) >> 7) & 0x01010101u);
        const unsigned g94 = (((0xDEDEDEDEu - q0) >> 7) & 0x01010101u)
                           + (((0xDEDEDEDEu - q1) >> 7) & 0x01010101u)
                           + (((0xDEDEDEDEu - q2) >> 7) & 0x01010101u)
                           + (((0xDEDEDEDEu - q3) >> 7) & 0x01010101u);
        const unsigned w30 = __reduce_add_sync(0xffffffffu, g30);  // bytes (bAP,bAQ,bAR,bAS)
        const unsigned w94 = __reduce_add_sync(0xffffffffu, g94);  // bytes (bBP,bBQ,bBR,bBS)

        // bucket base = bin<<8: bytes to halfword-high positions per pair
        const unsigned A2pq = __byte_perm(w30, 0, 0x1404);   // (0,bAP,0,bAQ)
        const unsigned B2pq = __byte_perm(w94, 0, 0x1404);
        const unsigned A2rs = __byte_perm(w30, 0, 0x3424);   // (0,bAR,0,bAS)
        const unsigned B2rs = __byte_perm(w94, 0, 0x3424);

        float s0, s1, s2, s3;
        const int pxP = px0 + 4 * i;
        if (exY | (pxP < 7) | (pxP + 3 >= W - 7)) {
            // window touches zero padding: 8 exact bisection steps inside bucket
            bisect_pair<7, 0>(a0, a1, a2, a3, A2pq, B2pq, s0, s1);
            bisect_pair<7, 0>(b0, b1, b2, b3, A2rs, B2rs, s2, s3);
        } else {
            // clean: 256-wide bucket direct, midpoint +-128 substitution
            bisect_pair<7, 8>(a0, a1, a2, a3, A2pq, B2pq, s0, s1);
            bisect_pair<7, 8>(b0, b1, b2, b3, A2rs, B2rs, s2, s3);
        }
        if (lane == 4 * i)     myscale = s0;
        if (lane == 4 * i + 1) myscale = s1;
        if (lane == 4 * i + 2) myscale = s2;
        if (lane == 4 * i + 3) myscale = s3;
    }

    out[(size_t)bz * H * W + py * W + px0 + lane] = centerf * myscale;
}

extern "C" void kernel_launch(void* const* d_in, const int* in_sizes, int n_in,
                              void* d_out, int out_size)
{
    const float* in = (const float*)d_in[0];
    float* out = (float*)d_out;
    const int H = 512, W = 512;
    const int B = in_sizes[0] / (H * W);

    dim3 grid(W / 32, H / 8, B);
    dim3 block(256);
    tmcfar_kernel<<<grid, block>>>(in, out, H, W);
}